// round 2
// baseline (speedup 1.0000x reference)
#include <cuda_runtime.h>
#include <math.h>
#include <stdint.h>

#define RUNS 512
#define WAYS 5
#define SHOT 5
#define NSUP 25
#define NQ   75
#define NF   100
#define NTOT 105
#define DIM  640
#define LAM  10.0f
#define ALPHA_ 0.7f
#define EPSV 1e-3f
#define MAXIT 1000

// ---------------- device scratch (static: no allocations allowed) ----------
__device__ float g_proto[RUNS][WAYS][DIM];
__device__ float g_Fp[RUNS][WAYS][DIM];     // masked proto rows (epoch 2)
__device__ float g_Pq0[RUNS][NQ][WAYS];     // initial Pq before sinkhorn1
__device__ float g_Zext[RUNS][NTOT][WAYS];  // extended Z (epoch 2, pre-solve)
__device__ float g_Z0[RUNS][NTOT][WAYS];    // solved Z, pre-sinkhorn2
__device__ int   g_B1[3];
__device__ int   g_B2;

__device__ __forceinline__ float wred(float v) {
  #pragma unroll
  for (int o = 16; o; o >>= 1) v += __shfl_down_sync(0xffffffffu, v, o);
  return v;
}

__global__ void kzero_kernel() {
  if (threadIdx.x < 3) g_B1[threadIdx.x] = 0;
  if (threadIdx.x == 3) g_B2 = 0;
}

// ---------------- KA: proto (epoch0), Pq0, sinkhorn1 pass-1 ----------------
__global__ __launch_bounds__(160) void ka_kernel(const float* __restrict__ xs,
                                                 const float* __restrict__ xq,
                                                 int epoch) {
  __shared__ float ps[WAYS][DIM];
  __shared__ float pn[WAYS];
  __shared__ float P[NQ][WAYS];
  __shared__ float u[NQ];
  __shared__ int sdelta;
  int run = blockIdx.x;
  int tid = threadIdx.x, w = tid >> 5, lane = tid & 31;
  const float* xsr = xs + (size_t)run * NSUP * DIM;
  const float* xqr = xq + (size_t)run * NQ * DIM;

  if (epoch == 0) {
    for (int idx = tid; idx < WAYS * DIM; idx += 160) {
      int k = idx / DIM, d = idx % DIM;
      float s = 0.f;
      #pragma unroll
      for (int sh = 0; sh < SHOT; sh++) s += xsr[(k * SHOT + sh) * DIM + d];
      float v = s / 5.0f;
      ps[k][d] = v;
      g_proto[run][k][d] = v;
    }
  } else {
    for (int idx = tid; idx < WAYS * DIM; idx += 160) {
      int k = idx / DIM, d = idx % DIM;
      ps[k][d] = g_proto[run][k][d];
    }
  }
  __syncthreads();

  { // proto norms (5 warps, warp w does k=w)
    float a = 0.f;
    for (int d = lane; d < DIM; d += 32) { float v = ps[w][d]; a += v * v; }
    a = wred(a);
    if (lane == 0) pn[w] = a;
  }
  __syncthreads();

  // Pq = exp(-LAM * d2(query, proto))
  for (int q = w; q < NQ; q += 5) {
    float a0=0,a1=0,a2=0,a3=0,a4=0,an=0;
    const float* xr = xqr + q * DIM;
    for (int d = lane; d < DIM; d += 32) {
      float x = xr[d];
      an += x*x;
      a0 += x*ps[0][d]; a1 += x*ps[1][d]; a2 += x*ps[2][d];
      a3 += x*ps[3][d]; a4 += x*ps[4][d];
    }
    an = wred(an); a0 = wred(a0); a1 = wred(a1); a2 = wred(a2); a3 = wred(a3); a4 = wred(a4);
    if (lane == 0) {
      float acc[5] = {a0,a1,a2,a3,a4};
      #pragma unroll
      for (int k = 0; k < WAYS; k++) {
        float d2 = fmaxf(an + pn[k] - 2.0f * acc[k], 0.0f);
        float v = expf(-LAM * d2);
        P[q][k] = v;
        g_Pq0[run][q][k] = v;
      }
    }
  }
  for (int t = tid; t < NQ; t += 160) u[t] = 0.f;
  __syncthreads();

  // sinkhorn pass-1 (n=75, c=15, no labeled rows): count bodies until converged
  int b = 0;
  for (;;) {
    if (tid == 0) sdelta = 0;
    __syncthreads();
    float rs = 0.f;
    if (tid < NQ) {
      rs = P[tid][0] + P[tid][1] + P[tid][2] + P[tid][3] + P[tid][4];
      atomicMax(&sdelta, __float_as_int(fabsf(u[tid] - rs)));
    }
    __syncthreads();
    float delta = __int_as_float(sdelta);
    if (!(delta > EPSV && b < MAXIT)) break;
    if (tid < NQ) {
      u[tid] = rs;
      float inv = 1.0f / rs;
      #pragma unroll
      for (int k = 0; k < WAYS; k++) P[tid][k] *= inv;
    }
    __syncthreads();
    if (tid < WAYS) {
      float cs = 0.f;
      for (int q = 0; q < NQ; q++) cs += P[q][tid];
      float f = 15.0f / cs;
      for (int q = 0; q < NQ; q++) P[q][tid] *= f;
    }
    __syncthreads();
    b++;
  }
  if (tid == 0) atomicMax(&g_B1[epoch], b);
}

// ---------------- KB: replay sinkhorn1, entropy, proto blend; epoch2 tail ---
__global__ __launch_bounds__(128) void kb_kernel(const float* __restrict__ xs,
                                                 const float* __restrict__ xq,
                                                 const int* __restrict__ ys,
                                                 int epoch) {
  __shared__ float P[NQ][WAYS];
  __shared__ float Z[NF][WAYS];
  __shared__ float ent[NF];
  __shared__ float cs[WAYS];
  __shared__ float psh[WAYS][DIM];
  __shared__ float pn2[WAYS];
  __shared__ float dp[WAYS][WAYS];
  __shared__ float score[WAYS], maskv[WAYS];
  __shared__ float omega_s;
  int run = blockIdx.x, tid = threadIdx.x;
  const int* ysr = ys + run * NSUP;
  const float* xsr = xs + (size_t)run * NSUP * DIM;
  const float* xqr = xq + (size_t)run * NQ * DIM;

  for (int idx = tid; idx < NQ * WAYS; idx += 128)
    ((float*)P)[idx] = ((const float*)g_Pq0[run])[idx];
  __syncthreads();

  int b1 = g_B1[epoch];
  for (int it = 0; it < b1; it++) {
    if (tid < NQ) {
      float rs = P[tid][0]+P[tid][1]+P[tid][2]+P[tid][3]+P[tid][4];
      float inv = 1.0f / rs;
      #pragma unroll
      for (int k = 0; k < WAYS; k++) P[tid][k] *= inv;
    }
    __syncthreads();
    if (tid < WAYS) {
      float csv = 0.f;
      for (int q = 0; q < NQ; q++) csv += P[q][tid];
      float f = 15.0f / csv;
      for (int q = 0; q < NQ; q++) P[q][tid] *= f;
    }
    __syncthreads();
  }

  // Z = [onehot(ys); Pq]
  for (int idx = tid; idx < NF * WAYS; idx += 128) {
    int i = idx / WAYS, k = idx % WAYS;
    float v = (i < NSUP) ? ((ysr[i] == k) ? 1.0f : 0.0f) : P[i - NSUP][k];
    Z[i][k] = v;
  }
  __syncthreads();

  // entropy per row (pre-weighting)
  if (tid < NF) {
    float p[WAYS], s = 0.f;
    #pragma unroll
    for (int k = 0; k < WAYS; k++) { p[k] = Z[tid][k] + 1e-12f; s += p[k]; }
    float H = 0.f;
    #pragma unroll
    for (int k = 0; k < WAYS; k++) { float q = p[k] / s; H -= q * logf(q); }
    ent[tid] = H / logf(5.0f);
  }
  __syncthreads();

  // Z *= (1 - ent)
  for (int idx = tid; idx < NF * WAYS; idx += 128) {
    int i = idx / WAYS;
    ((float*)Z)[idx] *= (1.0f - ent[i]);
  }
  __syncthreads();
  if (tid < WAYS) {
    float c = 0.f;
    for (int i = 0; i < NF; i++) c += Z[i][tid];
    cs[tid] = c;
  }
  __syncthreads();

  // new_proto + blend (threads over d, 5 cols per thread)
  #pragma unroll
  for (int dd = 0; dd < 5; dd++) {
    int dcol = tid + dd * 128;
    float a[WAYS] = {0.f,0.f,0.f,0.f,0.f};
    for (int i = 0; i < NF; i++) {
      float f = (i < NSUP) ? xsr[i * DIM + dcol] : xqr[(i - NSUP) * DIM + dcol];
      #pragma unroll
      for (int k = 0; k < WAYS; k++) a[k] += Z[i][k] * f;
    }
    #pragma unroll
    for (int k = 0; k < WAYS; k++) {
      float np = a[k] / cs[k];
      float pr = (1.0f - 0.6f) * g_proto[run][k][dcol] + 0.6f * np;
      g_proto[run][k][dcol] = pr;
      psh[k][dcol] = pr;
    }
  }

  if (epoch == 2) {
    __syncthreads();
    int w = tid >> 5, lane = tid & 31;
    for (int k = w; k < WAYS; k += 4) {
      float a = 0.f;
      for (int d = lane; d < DIM; d += 32) { float v = psh[k][d]; a += v * v; }
      a = wred(a);
      if (lane == 0) pn2[k] = a;
    }
    __syncthreads();
    for (int p = w; p < WAYS * WAYS; p += 4) {
      int ia = p / WAYS, ib = p % WAYS;
      float acc = 0.f;
      for (int d = lane; d < DIM; d += 32) acc += psh[ia][d] * psh[ib][d];
      acc = wred(acc);
      if (lane == 0) {
        float d2 = fmaxf(pn2[ia] + pn2[ib] - 2.0f * acc, 0.0f);
        dp[ia][ib] = expf(-LAM * d2);
      }
    }
    __syncthreads();
    if (tid < WAYS) {
      float p[WAYS], s = 0.f;
      #pragma unroll
      for (int k = 0; k < WAYS; k++) { p[k] = dp[tid][k] + 1e-12f; s += p[k]; }
      float H = 0.f;
      #pragma unroll
      for (int k = 0; k < WAYS; k++) { float q = p[k] / s; H -= q * logf(q); }
      score[tid] = H / logf(5.0f);
    }
    if (tid == 0) {
      float s = 0.f;
      for (int i = 0; i < NF; i++) s += ent[i];
      omega_s = s / 100.0f;
    }
    __syncthreads();
    if (tid < WAYS) maskv[tid] = (score[tid] < omega_s) ? 1.0f : 0.0f;
    __syncthreads();
    for (int idx = tid; idx < WAYS * DIM; idx += 128) {
      int k = idx / DIM, d = idx % DIM;
      g_Fp[run][k][d] = psh[k][d] * maskv[k];
    }
    for (int idx = tid; idx < NF * WAYS; idx += 128) {
      int i = idx / WAYS, k = idx % WAYS;
      g_Zext[run][i][k] = Z[i][k];
    }
    if (tid < WAYS * WAYS) {
      int ia = tid / WAYS, k = tid % WAYS;
      g_Zext[run][NF + ia][k] = dp[ia][k] * maskv[ia];
    }
  }
}

// ---------------- KC: Gram, graph, Cholesky solve, sinkhorn2 pass-1 --------
#define FROWS 112
#define KCHUNK 32
#define FPAD 33
#define KC_SMEM ((NTOT*NTOT + FROWS*FPAD) * 4)

__global__ __launch_bounds__(256) void kc_kernel(const float* __restrict__ xs,
                                                 const float* __restrict__ xq,
                                                 const int* __restrict__ ys) {
  extern __shared__ float sm[];
  float* As = sm;                   // NTOT*NTOT
  float* Fsh = sm + NTOT * NTOT;    // FROWS*FPAD
  __shared__ float n2[NTOT];
  __shared__ float Dm[NTOT];
  __shared__ float yv[NTOT][WAYS];
  __shared__ float u2[NTOT];
  __shared__ float piv;
  __shared__ int sdelta;

  int run = blockIdx.x, tid = threadIdx.x;
  int ti = tid >> 4, tj = tid & 15;
  const float* xsr = xs + (size_t)run * NSUP * DIM;
  const float* xqr = xq + (size_t)run * NQ * DIM;
  const int* ysr = ys + run * NSUP;

  float acc[7][7];
  #pragma unroll
  for (int r = 0; r < 7; r++)
    #pragma unroll
    for (int c = 0; c < 7; c++) acc[r][c] = 0.f;

  for (int c0 = 0; c0 < DIM; c0 += KCHUNK) {
    __syncthreads();
    for (int e = tid; e < FROWS * KCHUNK; e += 256) {
      int r = e >> 5, dd = e & 31;
      float v = 0.f;
      if (r < NSUP)       v = xsr[r * DIM + c0 + dd];
      else if (r < NF)    v = xqr[(r - NSUP) * DIM + c0 + dd];
      else if (r < NTOT)  v = g_Fp[run][r - NF][c0 + dd];
      Fsh[r * FPAD + dd] = v;
    }
    __syncthreads();
    for (int dd = 0; dd < KCHUNK; dd++) {
      float a[7], bv[7];
      #pragma unroll
      for (int r = 0; r < 7; r++) a[r] = Fsh[(ti * 7 + r) * FPAD + dd];
      #pragma unroll
      for (int c = 0; c < 7; c++) bv[c] = Fsh[(tj * 7 + c) * FPAD + dd];
      #pragma unroll
      for (int r = 0; r < 7; r++)
        #pragma unroll
        for (int c = 0; c < 7; c++) acc[r][c] += a[r] * bv[c];
    }
  }
  __syncthreads();
  #pragma unroll
  for (int r = 0; r < 7; r++)
    #pragma unroll
    for (int c = 0; c < 7; c++) {
      int i = ti * 7 + r, j = tj * 7 + c;
      if (i < NTOT && j < NTOT) As[i * NTOT + j] = acc[r][c];
    }
  __syncthreads();
  if (tid < NTOT) n2[tid] = As[tid * NTOT + tid];
  __syncthreads();

  // S -> W = exp(-LAM*d2), zero diag
  for (int idx = tid; idx < NTOT * NTOT; idx += 256) {
    int i = idx / NTOT, j = idx % NTOT;
    float wv = 0.f;
    if (i != j) {
      float d2 = fmaxf(n2[i] + n2[j] - 2.0f * As[idx], 0.0f);
      wv = expf(-LAM * d2);
    }
    As[idx] = wv;
  }
  __syncthreads();
  if (tid < NTOT) {
    float s = 0.f;
    for (int j = 0; j < NTOT; j++) s += As[tid * NTOT + j];
    Dm[tid] = 1.0f / sqrtf(s);
  }
  __syncthreads();
  // A = I - ALPHA * Dm_i * W * Dm_j
  for (int idx = tid; idx < NTOT * NTOT; idx += 256) {
    int i = idx / NTOT, j = idx % NTOT;
    float v = (Dm[j] * As[idx]) * Dm[i];
    As[idx] = ((i == j) ? 1.0f : 0.0f) - ALPHA_ * v;
  }
  __syncthreads();

  // Cholesky (in place, lower; updates full trailing square for simple index)
  for (int j = 0; j < NTOT; j++) {
    if (tid == 0) piv = sqrtf(As[j * NTOT + j]);
    __syncthreads();
    float pv = piv;
    for (int i = j + 1 + tid; i < NTOT; i += 256) As[i * NTOT + j] /= pv;
    if (tid == 0) As[j * NTOT + j] = pv;
    __syncthreads();
    int m = NTOT - 1 - j;
    for (int idx = tid; idx < m * m; idx += 256) {
      int i = j + 1 + idx / m, k = j + 1 + idx % m;
      As[i * NTOT + k] -= As[i * NTOT + j] * As[k * NTOT + j];
    }
    __syncthreads();
  }

  // load RHS
  for (int idx = tid; idx < NTOT * WAYS; idx += 256)
    ((float*)yv)[idx] = ((const float*)g_Zext[run])[idx];
  __syncthreads();
  // forward solve L y = b
  for (int j = 0; j < NTOT; j++) {
    if (tid < WAYS) yv[j][tid] /= As[j * NTOT + j];
    __syncthreads();
    int m = NTOT - 1 - j;
    for (int idx = tid; idx < m * WAYS; idx += 256) {
      int i = j + 1 + idx / WAYS, k = idx % WAYS;
      yv[i][k] -= As[i * NTOT + j] * yv[j][k];
    }
    __syncthreads();
  }
  // backward solve L^T x = y
  for (int j = NTOT - 1; j >= 0; j--) {
    if (tid < WAYS) yv[j][tid] /= As[j * NTOT + j];
    __syncthreads();
    for (int idx = tid; idx < j * WAYS; idx += 256) {
      int i = idx / WAYS, k = idx % WAYS;
      yv[i][k] -= As[j * NTOT + i] * yv[j][k];
    }
    __syncthreads();
  }
  for (int idx = tid; idx < NTOT * WAYS; idx += 256)
    ((float*)g_Z0[run])[idx] = ((float*)yv)[idx];
  if (tid < NTOT) u2[tid] = 0.f;
  __syncthreads();

  // sinkhorn2 pass-1 (n=105, c=21, n_l=25)
  int b = 0;
  for (;;) {
    if (tid == 0) sdelta = 0;
    __syncthreads();
    float rs = 0.f;
    if (tid < NTOT) {
      rs = yv[tid][0]+yv[tid][1]+yv[tid][2]+yv[tid][3]+yv[tid][4];
      atomicMax(&sdelta, __float_as_int(fabsf(u2[tid] - rs)));
    }
    __syncthreads();
    float delta = __int_as_float(sdelta);
    if (!(delta > EPSV && b < MAXIT)) break;
    if (tid < NTOT) {
      u2[tid] = rs;
      float inv = 1.0f / rs;
      #pragma unroll
      for (int k = 0; k < WAYS; k++) yv[tid][k] *= inv;
    }
    __syncthreads();
    if (tid < WAYS) {
      float csv = 0.f;
      for (int i = 0; i < NTOT; i++) csv += yv[i][tid];
      float f = 21.0f / csv;
      for (int i = 0; i < NTOT; i++) yv[i][tid] *= f;
    }
    __syncthreads();
    if (tid < NSUP) {
      int cls = ysr[tid];
      #pragma unroll
      for (int k = 0; k < WAYS; k++) yv[tid][k] = (k == cls) ? 1.0f : 0.0f;
    }
    __syncthreads();
    b++;
  }
  if (tid == 0) atomicMax(&g_B2, b);
}

// ---------------- KD: replay sinkhorn2, argmax, accuracy -------------------
__global__ __launch_bounds__(128) void kd_kernel(const int* __restrict__ ys,
                                                 const int* __restrict__ yq,
                                                 float* __restrict__ out) {
  __shared__ float P[NTOT][WAYS];
  __shared__ int cnt;
  int run = blockIdx.x, tid = threadIdx.x;
  const int* ysr = ys + run * NSUP;
  for (int idx = tid; idx < NTOT * WAYS; idx += 128)
    ((float*)P)[idx] = ((const float*)g_Z0[run])[idx];
  __syncthreads();
  int b2 = g_B2;
  for (int it = 0; it < b2; it++) {
    if (tid < NTOT) {
      float rs = P[tid][0]+P[tid][1]+P[tid][2]+P[tid][3]+P[tid][4];
      float inv = 1.0f / rs;
      #pragma unroll
      for (int k = 0; k < WAYS; k++) P[tid][k] *= inv;
    }
    __syncthreads();
    if (tid < WAYS) {
      float csv = 0.f;
      for (int i = 0; i < NTOT; i++) csv += P[i][tid];
      float f = 21.0f / csv;
      for (int i = 0; i < NTOT; i++) P[i][tid] *= f;
    }
    __syncthreads();
    if (tid < NSUP) {
      int cls = ysr[tid];
      #pragma unroll
      for (int k = 0; k < WAYS; k++) P[tid][k] = (k == cls) ? 1.0f : 0.0f;
    }
    __syncthreads();
  }
  if (tid == 0) cnt = 0;
  __syncthreads();
  if (tid < NQ) {
    int i = NSUP + tid;
    float best = P[i][0]; int bi = 0;
    #pragma unroll
    for (int k = 1; k < WAYS; k++)
      if (P[i][k] > best) { best = P[i][k]; bi = k; }
    if (bi == yq[run * NQ + tid]) atomicAdd(&cnt, 1);
  }
  __syncthreads();
  if (tid == 0) out[run] = (float)cnt / 75.0f;
}

// ---------------------------------------------------------------------------
extern "C" void kernel_launch(void* const* d_in, const int* in_sizes, int n_in,
                              void* d_out, int out_size) {
  const float* xs = (const float*)d_in[0];
  const float* xq = (const float*)d_in[1];
  const int*   ys = (const int*)d_in[2];
  const int*   yq = (const int*)d_in[3];
  float* out = (float*)d_out;

  cudaFuncSetAttribute(kc_kernel, cudaFuncAttributeMaxDynamicSharedMemorySize,
                       KC_SMEM);

  kzero_kernel<<<1, 32>>>();
  for (int e = 0; e < 3; e++) {
    ka_kernel<<<RUNS, 160>>>(xs, xq, e);
    kb_kernel<<<RUNS, 128>>>(xs, xq, ys, e);
  }
  kc_kernel<<<RUNS, 256, KC_SMEM>>>(xs, xq, ys);
  kd_kernel<<<RUNS, 128>>>(ys, yq, out);
}

// round 4
// speedup vs baseline: 1.0020x; 1.0020x over previous
#include <cuda_runtime.h>
#include <math.h>
#include <stdint.h>

#define RUNS 512
#define WAYS 5
#define SHOT 5
#define NSUP 25
#define NQ   75
#define NF   100
#define NTOT 105
#define DIM  640
#define LAM  10.0f
#define ALPHA_ 0.7f
#define EPSV 1e-3f
#define MAXIT 1000

// ---------------- device scratch (static: no allocations allowed) ----------
__device__ float g_proto[RUNS][WAYS][DIM];
__device__ float g_Fp[RUNS][WAYS][DIM];     // masked proto rows (epoch 2)
__device__ float g_Pq0[RUNS][NQ][WAYS];     // initial Pq before sinkhorn1
__device__ float g_Zext[RUNS][NTOT][WAYS];  // extended Z (epoch 2, pre-solve)
__device__ float g_Z0[RUNS][NTOT][WAYS];    // solved Z, pre-sinkhorn2
__device__ int   g_B1[3];
__device__ int   g_B2;

__device__ __forceinline__ float wred(float v) {
  #pragma unroll
  for (int o = 16; o; o >>= 1) v += __shfl_down_sync(0xffffffffu, v, o);
  return v;
}

__global__ void kzero_kernel() {
  if (threadIdx.x < 3) g_B1[threadIdx.x] = 0;
  if (threadIdx.x == 3) g_B2 = 0;
}

// ---------------- KA: proto (epoch0), Pq0, sinkhorn1 pass-1 ----------------
__global__ __launch_bounds__(160) void ka_kernel(const float* __restrict__ xs,
                                                 const float* __restrict__ xq,
                                                 int epoch) {
  __shared__ float ps[WAYS][DIM];
  __shared__ float pn[WAYS];
  __shared__ float P[NQ][WAYS];
  __shared__ float u[NQ];
  __shared__ int sdelta;
  int run = blockIdx.x;
  int tid = threadIdx.x, w = tid >> 5, lane = tid & 31;
  const float* xsr = xs + (size_t)run * NSUP * DIM;
  const float* xqr = xq + (size_t)run * NQ * DIM;

  if (epoch == 0) {
    for (int idx = tid; idx < WAYS * DIM; idx += 160) {
      int k = idx / DIM, d = idx % DIM;
      float s = 0.f;
      #pragma unroll
      for (int sh = 0; sh < SHOT; sh++) s += xsr[(k * SHOT + sh) * DIM + d];
      float v = s / 5.0f;
      ps[k][d] = v;
      g_proto[run][k][d] = v;
    }
  } else {
    for (int idx = tid; idx < WAYS * DIM; idx += 160) {
      int k = idx / DIM, d = idx % DIM;
      ps[k][d] = g_proto[run][k][d];
    }
  }
  __syncthreads();

  { // proto norms (5 warps, warp w does k=w)
    float a = 0.f;
    for (int d = lane; d < DIM; d += 32) { float v = ps[w][d]; a += v * v; }
    a = wred(a);
    if (lane == 0) pn[w] = a;
  }
  __syncthreads();

  // Pq = exp(-LAM * d2(query, proto))
  for (int q = w; q < NQ; q += 5) {
    float a0=0,a1=0,a2=0,a3=0,a4=0,an=0;
    const float* xr = xqr + q * DIM;
    for (int d = lane; d < DIM; d += 32) {
      float x = xr[d];
      an += x*x;
      a0 += x*ps[0][d]; a1 += x*ps[1][d]; a2 += x*ps[2][d];
      a3 += x*ps[3][d]; a4 += x*ps[4][d];
    }
    an = wred(an); a0 = wred(a0); a1 = wred(a1); a2 = wred(a2); a3 = wred(a3); a4 = wred(a4);
    if (lane == 0) {
      float acc[5] = {a0,a1,a2,a3,a4};
      #pragma unroll
      for (int k = 0; k < WAYS; k++) {
        float d2 = fmaxf(an + pn[k] - 2.0f * acc[k], 0.0f);
        float v = expf(-LAM * d2);
        P[q][k] = v;
        g_Pq0[run][q][k] = v;
      }
    }
  }
  for (int t = tid; t < NQ; t += 160) u[t] = 0.f;
  __syncthreads();

  // sinkhorn pass-1 (n=75, c=15, no labeled rows): count bodies until converged
  int b = 0;
  for (;;) {
    if (tid == 0) sdelta = 0;
    __syncthreads();
    float rs = 0.f;
    if (tid < NQ) {
      rs = P[tid][0] + P[tid][1] + P[tid][2] + P[tid][3] + P[tid][4];
      atomicMax(&sdelta, __float_as_int(fabsf(u[tid] - rs)));
    }
    __syncthreads();
    float delta = __int_as_float(sdelta);
    if (!(delta > EPSV && b < MAXIT)) break;
    if (tid < NQ) {
      u[tid] = rs;
      float inv = 1.0f / rs;
      #pragma unroll
      for (int k = 0; k < WAYS; k++) P[tid][k] *= inv;
    }
    __syncthreads();
    if (tid < WAYS) {
      float cs = 0.f;
      for (int q = 0; q < NQ; q++) cs += P[q][tid];
      float f = 15.0f / cs;
      for (int q = 0; q < NQ; q++) P[q][tid] *= f;
    }
    __syncthreads();
    b++;
  }
  if (tid == 0) atomicMax(&g_B1[epoch], b);
}

// ---------------- KB: replay sinkhorn1, entropy, proto blend; epoch2 tail ---
__global__ __launch_bounds__(128) void kb_kernel(const float* __restrict__ xs,
                                                 const float* __restrict__ xq,
                                                 const int* __restrict__ ys,
                                                 int epoch) {
  __shared__ float P[NQ][WAYS];
  __shared__ float Z[NF][WAYS];
  __shared__ float ent[NF];
  __shared__ float cs[WAYS];
  __shared__ float psh[WAYS][DIM];
  __shared__ float pn2[WAYS];
  __shared__ float dp[WAYS][WAYS];
  __shared__ float score[WAYS], maskv[WAYS];
  __shared__ float omega_s;
  int run = blockIdx.x, tid = threadIdx.x;
  const int* ysr = ys + run * NSUP;
  const float* xsr = xs + (size_t)run * NSUP * DIM;
  const float* xqr = xq + (size_t)run * NQ * DIM;

  for (int idx = tid; idx < NQ * WAYS; idx += 128)
    ((float*)P)[idx] = ((const float*)g_Pq0[run])[idx];
  __syncthreads();

  int b1 = g_B1[epoch];
  for (int it = 0; it < b1; it++) {
    if (tid < NQ) {
      float rs = P[tid][0]+P[tid][1]+P[tid][2]+P[tid][3]+P[tid][4];
      float inv = 1.0f / rs;
      #pragma unroll
      for (int k = 0; k < WAYS; k++) P[tid][k] *= inv;
    }
    __syncthreads();
    if (tid < WAYS) {
      float csv = 0.f;
      for (int q = 0; q < NQ; q++) csv += P[q][tid];
      float f = 15.0f / csv;
      for (int q = 0; q < NQ; q++) P[q][tid] *= f;
    }
    __syncthreads();
  }

  // Z = [onehot(ys); Pq]
  for (int idx = tid; idx < NF * WAYS; idx += 128) {
    int i = idx / WAYS, k = idx % WAYS;
    float v = (i < NSUP) ? ((ysr[i] == k) ? 1.0f : 0.0f) : P[i - NSUP][k];
    Z[i][k] = v;
  }
  __syncthreads();

  // entropy per row (pre-weighting)
  if (tid < NF) {
    float p[WAYS], s = 0.f;
    #pragma unroll
    for (int k = 0; k < WAYS; k++) { p[k] = Z[tid][k] + 1e-12f; s += p[k]; }
    float H = 0.f;
    #pragma unroll
    for (int k = 0; k < WAYS; k++) { float q = p[k] / s; H -= q * logf(q); }
    ent[tid] = H / logf(5.0f);
  }
  __syncthreads();

  // Z *= (1 - ent)
  for (int idx = tid; idx < NF * WAYS; idx += 128) {
    int i = idx / WAYS;
    ((float*)Z)[idx] *= (1.0f - ent[i]);
  }
  __syncthreads();
  if (tid < WAYS) {
    float c = 0.f;
    for (int i = 0; i < NF; i++) c += Z[i][tid];
    cs[tid] = c;
  }
  __syncthreads();

  // new_proto + blend (threads over d, 5 cols per thread)
  #pragma unroll
  for (int dd = 0; dd < 5; dd++) {
    int dcol = tid + dd * 128;
    float a[WAYS] = {0.f,0.f,0.f,0.f,0.f};
    for (int i = 0; i < NF; i++) {
      float f = (i < NSUP) ? xsr[i * DIM + dcol] : xqr[(i - NSUP) * DIM + dcol];
      #pragma unroll
      for (int k = 0; k < WAYS; k++) a[k] += Z[i][k] * f;
    }
    #pragma unroll
    for (int k = 0; k < WAYS; k++) {
      float np = a[k] / cs[k];
      float pr = (1.0f - 0.6f) * g_proto[run][k][dcol] + 0.6f * np;
      g_proto[run][k][dcol] = pr;
      psh[k][dcol] = pr;
    }
  }

  if (epoch == 2) {
    __syncthreads();
    int w = tid >> 5, lane = tid & 31;
    for (int k = w; k < WAYS; k += 4) {
      float a = 0.f;
      for (int d = lane; d < DIM; d += 32) { float v = psh[k][d]; a += v * v; }
      a = wred(a);
      if (lane == 0) pn2[k] = a;
    }
    __syncthreads();
    for (int p = w; p < WAYS * WAYS; p += 4) {
      int ia = p / WAYS, ib = p % WAYS;
      float acc = 0.f;
      for (int d = lane; d < DIM; d += 32) acc += psh[ia][d] * psh[ib][d];
      acc = wred(acc);
      if (lane == 0) {
        float d2 = fmaxf(pn2[ia] + pn2[ib] - 2.0f * acc, 0.0f);
        dp[ia][ib] = expf(-LAM * d2);
      }
    }
    __syncthreads();
    if (tid < WAYS) {
      float p[WAYS], s = 0.f;
      #pragma unroll
      for (int k = 0; k < WAYS; k++) { p[k] = dp[tid][k] + 1e-12f; s += p[k]; }
      float H = 0.f;
      #pragma unroll
      for (int k = 0; k < WAYS; k++) { float q = p[k] / s; H -= q * logf(q); }
      score[tid] = H / logf(5.0f);
    }
    if (tid == 0) {
      float s = 0.f;
      for (int i = 0; i < NF; i++) s += ent[i];
      omega_s = s / 100.0f;
    }
    __syncthreads();
    if (tid < WAYS) maskv[tid] = (score[tid] < omega_s) ? 1.0f : 0.0f;
    __syncthreads();
    for (int idx = tid; idx < WAYS * DIM; idx += 128) {
      int k = idx / DIM, d = idx % DIM;
      g_Fp[run][k][d] = psh[k][d] * maskv[k];
    }
    for (int idx = tid; idx < NF * WAYS; idx += 128) {
      int i = idx / WAYS, k = idx % WAYS;
      g_Zext[run][i][k] = Z[i][k];
    }
    if (tid < WAYS * WAYS) {
      int ia = tid / WAYS, k = tid % WAYS;
      g_Zext[run][NF + ia][k] = dp[ia][k] * maskv[ia];
    }
  }
}

// ---------------- KC: Gram, graph, Cholesky solve, sinkhorn2 pass-1 --------
#define FROWS 112
#define KCHUNK 32
#define FPAD 33
#define KC_SMEM ((NTOT*NTOT + FROWS*FPAD) * 4)

__global__ __launch_bounds__(256) void kc_kernel(const float* __restrict__ xs,
                                                 const float* __restrict__ xq,
                                                 const int* __restrict__ ys) {
  extern __shared__ float sm[];
  float* As = sm;                   // NTOT*NTOT
  float* Fsh = sm + NTOT * NTOT;    // FROWS*FPAD
  __shared__ float n2[NTOT];
  __shared__ float Dm[NTOT];
  __shared__ float yv[NTOT][WAYS];
  __shared__ float u2[NTOT];
  __shared__ float piv;
  __shared__ int sdelta;

  int run = blockIdx.x, tid = threadIdx.x;
  int ti = tid >> 4, tj = tid & 15;
  const float* xsr = xs + (size_t)run * NSUP * DIM;
  const float* xqr = xq + (size_t)run * NQ * DIM;
  const int* ysr = ys + run * NSUP;

  float acc[7][7];
  #pragma unroll
  for (int r = 0; r < 7; r++)
    #pragma unroll
    for (int c = 0; c < 7; c++) acc[r][c] = 0.f;

  for (int c0 = 0; c0 < DIM; c0 += KCHUNK) {
    __syncthreads();
    for (int e = tid; e < FROWS * KCHUNK; e += 256) {
      int r = e >> 5, dd = e & 31;
      float v = 0.f;
      if (r < NSUP)       v = xsr[r * DIM + c0 + dd];
      else if (r < NF)    v = xqr[(r - NSUP) * DIM + c0 + dd];
      else if (r < NTOT)  v = g_Fp[run][r - NF][c0 + dd];
      Fsh[r * FPAD + dd] = v;
    }
    __syncthreads();
    for (int dd = 0; dd < KCHUNK; dd++) {
      float a[7], bv[7];
      #pragma unroll
      for (int r = 0; r < 7; r++) a[r] = Fsh[(ti * 7 + r) * FPAD + dd];
      #pragma unroll
      for (int c = 0; c < 7; c++) bv[c] = Fsh[(tj * 7 + c) * FPAD + dd];
      #pragma unroll
      for (int r = 0; r < 7; r++)
        #pragma unroll
        for (int c = 0; c < 7; c++) acc[r][c] += a[r] * bv[c];
    }
  }
  __syncthreads();
  #pragma unroll
  for (int r = 0; r < 7; r++)
    #pragma unroll
    for (int c = 0; c < 7; c++) {
      int i = ti * 7 + r, j = tj * 7 + c;
      if (i < NTOT && j < NTOT) As[i * NTOT + j] = acc[r][c];
    }
  __syncthreads();
  if (tid < NTOT) n2[tid] = As[tid * NTOT + tid];
  __syncthreads();

  // S -> W = exp(-LAM*d2), zero diag
  for (int idx = tid; idx < NTOT * NTOT; idx += 256) {
    int i = idx / NTOT, j = idx % NTOT;
    float wv = 0.f;
    if (i != j) {
      float d2 = fmaxf(n2[i] + n2[j] - 2.0f * As[idx], 0.0f);
      wv = expf(-LAM * d2);
    }
    As[idx] = wv;
  }
  __syncthreads();
  if (tid < NTOT) {
    float s = 0.f;
    for (int j = 0; j < NTOT; j++) s += As[tid * NTOT + j];
    Dm[tid] = 1.0f / sqrtf(s);
  }
  __syncthreads();
  // A = I - ALPHA * Dm_i * W * Dm_j
  for (int idx = tid; idx < NTOT * NTOT; idx += 256) {
    int i = idx / NTOT, j = idx % NTOT;
    float v = (Dm[j] * As[idx]) * Dm[i];
    As[idx] = ((i == j) ? 1.0f : 0.0f) - ALPHA_ * v;
  }
  __syncthreads();

  // Cholesky (in place, lower; updates full trailing square for simple index)
  for (int j = 0; j < NTOT; j++) {
    if (tid == 0) piv = sqrtf(As[j * NTOT + j]);
    __syncthreads();
    float pv = piv;
    for (int i = j + 1 + tid; i < NTOT; i += 256) As[i * NTOT + j] /= pv;
    if (tid == 0) As[j * NTOT + j] = pv;
    __syncthreads();
    int m = NTOT - 1 - j;
    for (int idx = tid; idx < m * m; idx += 256) {
      int i = j + 1 + idx / m, k = j + 1 + idx % m;
      As[i * NTOT + k] -= As[i * NTOT + j] * As[k * NTOT + j];
    }
    __syncthreads();
  }

  // load RHS
  for (int idx = tid; idx < NTOT * WAYS; idx += 256)
    ((float*)yv)[idx] = ((const float*)g_Zext[run])[idx];
  __syncthreads();
  // forward solve L y = b
  for (int j = 0; j < NTOT; j++) {
    if (tid < WAYS) yv[j][tid] /= As[j * NTOT + j];
    __syncthreads();
    int m = NTOT - 1 - j;
    for (int idx = tid; idx < m * WAYS; idx += 256) {
      int i = j + 1 + idx / WAYS, k = idx % WAYS;
      yv[i][k] -= As[i * NTOT + j] * yv[j][k];
    }
    __syncthreads();
  }
  // backward solve L^T x = y
  for (int j = NTOT - 1; j >= 0; j--) {
    if (tid < WAYS) yv[j][tid] /= As[j * NTOT + j];
    __syncthreads();
    for (int idx = tid; idx < j * WAYS; idx += 256) {
      int i = idx / WAYS, k = idx % WAYS;
      yv[i][k] -= As[j * NTOT + i] * yv[j][k];
    }
    __syncthreads();
  }
  for (int idx = tid; idx < NTOT * WAYS; idx += 256)
    ((float*)g_Z0[run])[idx] = ((float*)yv)[idx];
  if (tid < NTOT) u2[tid] = 0.f;
  __syncthreads();

  // sinkhorn2 pass-1 (n=105, c=21, n_l=25)
  int b = 0;
  for (;;) {
    if (tid == 0) sdelta = 0;
    __syncthreads();
    float rs = 0.f;
    if (tid < NTOT) {
      rs = yv[tid][0]+yv[tid][1]+yv[tid][2]+yv[tid][3]+yv[tid][4];
      atomicMax(&sdelta, __float_as_int(fabsf(u2[tid] - rs)));
    }
    __syncthreads();
    float delta = __int_as_float(sdelta);
    if (!(delta > EPSV && b < MAXIT)) break;
    if (tid < NTOT) {
      u2[tid] = rs;
      float inv = 1.0f / rs;
      #pragma unroll
      for (int k = 0; k < WAYS; k++) yv[tid][k] *= inv;
    }
    __syncthreads();
    if (tid < WAYS) {
      float csv = 0.f;
      for (int i = 0; i < NTOT; i++) csv += yv[i][tid];
      float f = 21.0f / csv;
      for (int i = 0; i < NTOT; i++) yv[i][tid] *= f;
    }
    __syncthreads();
    if (tid < NSUP) {
      int cls = ysr[tid];
      #pragma unroll
      for (int k = 0; k < WAYS; k++) yv[tid][k] = (k == cls) ? 1.0f : 0.0f;
    }
    __syncthreads();
    b++;
  }
  if (tid == 0) atomicMax(&g_B2, b);
}

// ---------------- KD: replay sinkhorn2, argmax, accuracy -------------------
__global__ __launch_bounds__(128) void kd_kernel(const int* __restrict__ ys,
                                                 const int* __restrict__ yq,
                                                 float* __restrict__ out) {
  __shared__ float P[NTOT][WAYS];
  __shared__ int cnt;
  int run = blockIdx.x, tid = threadIdx.x;
  const int* ysr = ys + run * NSUP;
  for (int idx = tid; idx < NTOT * WAYS; idx += 128)
    ((float*)P)[idx] = ((const float*)g_Z0[run])[idx];
  __syncthreads();
  int b2 = g_B2;
  for (int it = 0; it < b2; it++) {
    if (tid < NTOT) {
      float rs = P[tid][0]+P[tid][1]+P[tid][2]+P[tid][3]+P[tid][4];
      float inv = 1.0f / rs;
      #pragma unroll
      for (int k = 0; k < WAYS; k++) P[tid][k] *= inv;
    }
    __syncthreads();
    if (tid < WAYS) {
      float csv = 0.f;
      for (int i = 0; i < NTOT; i++) csv += P[i][tid];
      float f = 21.0f / csv;
      for (int i = 0; i < NTOT; i++) P[i][tid] *= f;
    }
    __syncthreads();
    if (tid < NSUP) {
      int cls = ysr[tid];
      #pragma unroll
      for (int k = 0; k < WAYS; k++) P[tid][k] = (k == cls) ? 1.0f : 0.0f;
    }
    __syncthreads();
  }
  if (tid == 0) cnt = 0;
  __syncthreads();
  if (tid < NQ) {
    int i = NSUP + tid;
    float best = P[i][0]; int bi = 0;
    #pragma unroll
    for (int k = 1; k < WAYS; k++)
      if (P[i][k] > best) { best = P[i][k]; bi = k; }
    if (bi == yq[run * NQ + tid]) atomicAdd(&cnt, 1);
  }
  __syncthreads();
  if (tid == 0) out[run] = (float)cnt / 75.0f;
}

// ---------------------------------------------------------------------------
extern "C" void kernel_launch(void* const* d_in, const int* in_sizes, int n_in,
                              void* d_out, int out_size) {
  const float* xs = (const float*)d_in[0];
  const float* xq = (const float*)d_in[1];
  const int*   ys = (const int*)d_in[2];
  const int*   yq = (const int*)d_in[3];
  float* out = (float*)d_out;

  cudaFuncSetAttribute(kc_kernel, cudaFuncAttributeMaxDynamicSharedMemorySize,
                       KC_SMEM);

  kzero_kernel<<<1, 32>>>();
  for (int e = 0; e < 3; e++) {
    ka_kernel<<<RUNS, 160>>>(xs, xq, e);
    kb_kernel<<<RUNS, 128>>>(xs, xq, ys, e);
  }
  kc_kernel<<<RUNS, 256, KC_SMEM>>>(xs, xq, ys);
  kd_kernel<<<RUNS, 128>>>(ys, yq, out);
}

// round 5
// speedup vs baseline: 1.0161x; 1.0141x over previous
#include <cuda_runtime.h>
#include <math.h>
#include <stdint.h>

#define RUNS 512
#define WAYS 5
#define SHOT 5
#define NSUP 25
#define NQ   75
#define NF   100
#define NTOT 105
#define DIM  640
#define LAM  10.0f
#define ALPHA_ 0.7f
#define EPSV 1e-3f
#define MAXIT 1000

// ---------------- device scratch (static: no allocations allowed) ----------
__device__ float g_proto[RUNS][WAYS][DIM];
__device__ float g_Fp[RUNS][WAYS][DIM];     // masked proto rows (epoch 2)
__device__ float g_P1[RUNS][NQ][WAYS];      // sinkhorn1 state after pass-1
__device__ int   g_b1run[RUNS];             // per-run pass-1 body count
__device__ float g_Zext[RUNS][NTOT][WAYS];  // extended Z (epoch 2, pre-solve)
__device__ float g_Z0[RUNS][NTOT][WAYS];    // sinkhorn2 state after pass-1
__device__ int   g_b2run[RUNS];
__device__ int   g_B1[3];
__device__ int   g_B2;

__device__ __forceinline__ float wred(float v) {
  #pragma unroll
  for (int o = 16; o; o >>= 1) v += __shfl_down_sync(0xffffffffu, v, o);
  return v;
}

__global__ void kzero_kernel() {
  if (threadIdx.x < 3) g_B1[threadIdx.x] = 0;
  if (threadIdx.x == 3) g_B2 = 0;
}

// ---------------- KA: proto load, Pq0, sinkhorn1 pass-1 (save state) -------
__global__ __launch_bounds__(160) void ka_kernel(const float* __restrict__ xs,
                                                 const float* __restrict__ xq,
                                                 int epoch) {
  __shared__ float ps[WAYS][DIM];
  __shared__ float pn[WAYS];
  __shared__ float P[NQ][WAYS];
  __shared__ float u[NQ];
  __shared__ int sdelta;
  int run = blockIdx.x;
  int tid = threadIdx.x, w = tid >> 5, lane = tid & 31;
  const float* xsr = xs + (size_t)run * NSUP * DIM;
  const float* xqr = xq + (size_t)run * NQ * DIM;

  if (epoch == 0) {
    for (int idx = tid; idx < WAYS * DIM; idx += 160) {
      int k = idx / DIM, d = idx % DIM;
      float s = 0.f;
      #pragma unroll
      for (int sh = 0; sh < SHOT; sh++) s += xsr[(k * SHOT + sh) * DIM + d];
      float v = s / 5.0f;
      ps[k][d] = v;
      g_proto[run][k][d] = v;
    }
  } else {
    for (int idx = tid; idx < WAYS * DIM; idx += 160) {
      int k = idx / DIM, d = idx % DIM;
      ps[k][d] = g_proto[run][k][d];
    }
  }
  __syncthreads();

  { // proto norms (warp w does class w)
    float a = 0.f;
    for (int d = lane; d < DIM; d += 32) { float v = ps[w][d]; a += v * v; }
    a = wred(a);
    if (lane == 0) pn[w] = a;
  }
  __syncthreads();

  // Pq = exp(-LAM * d2(query, proto))
  for (int q = w; q < NQ; q += 5) {
    float a0=0,a1=0,a2=0,a3=0,a4=0,an=0;
    const float* xr = xqr + q * DIM;
    for (int d = lane; d < DIM; d += 32) {
      float x = xr[d];
      an += x*x;
      a0 += x*ps[0][d]; a1 += x*ps[1][d]; a2 += x*ps[2][d];
      a3 += x*ps[3][d]; a4 += x*ps[4][d];
    }
    an = wred(an); a0 = wred(a0); a1 = wred(a1); a2 = wred(a2); a3 = wred(a3); a4 = wred(a4);
    if (lane == 0) {
      float acc[5] = {a0,a1,a2,a3,a4};
      #pragma unroll
      for (int k = 0; k < WAYS; k++) {
        float d2 = fmaxf(an + pn[k] - 2.0f * acc[k], 0.0f);
        P[q][k] = expf(-LAM * d2);
      }
    }
  }
  for (int t = tid; t < NQ; t += 160) u[t] = 0.f;
  __syncthreads();

  // sinkhorn pass-1 (n=75, c=15): count bodies, warp-parallel column step
  int b = 0;
  for (;;) {
    if (tid == 0) sdelta = 0;
    __syncthreads();
    float rs = 0.f;
    if (tid < NQ) {
      rs = P[tid][0] + P[tid][1] + P[tid][2] + P[tid][3] + P[tid][4];
      atomicMax(&sdelta, __float_as_int(fabsf(u[tid] - rs)));
    }
    __syncthreads();
    float delta = __int_as_float(sdelta);
    if (!(delta > EPSV && b < MAXIT)) break;
    if (tid < NQ) {
      u[tid] = rs;
      float inv = 1.0f / rs;
      #pragma unroll
      for (int k = 0; k < WAYS; k++) P[tid][k] *= inv;
    }
    __syncthreads();
    { // warp w normalizes column w
      float part = 0.f;
      for (int i = lane; i < NQ; i += 32) part += P[i][w];
      part = wred(part);
      float f = __shfl_sync(0xffffffffu, 15.0f / part, 0);
      for (int i = lane; i < NQ; i += 32) P[i][w] *= f;
    }
    __syncthreads();
    b++;
  }
  if (tid == 0) { atomicMax(&g_B1[epoch], b); g_b1run[run] = b; }
  // save post-pass-1 state: replay only continues from here
  for (int idx = tid; idx < NQ * WAYS; idx += 160)
    ((float*)g_P1[run])[idx] = ((float*)P)[idx];
}

// ---------------- KB: continue sinkhorn1, entropy, proto blend; epoch2 tail
__global__ __launch_bounds__(160) void kb_kernel(const float* __restrict__ xs,
                                                 const float* __restrict__ xq,
                                                 const int* __restrict__ ys,
                                                 int epoch) {
  __shared__ float P[NQ][WAYS];
  __shared__ float Z[NF][WAYS];
  __shared__ float ent[NF];
  __shared__ float cs[WAYS];
  __shared__ float psh[WAYS][DIM];
  __shared__ float pn2[WAYS];
  __shared__ float dp[WAYS][WAYS];
  __shared__ float score[WAYS], maskv[WAYS];
  __shared__ float omega_s;
  int run = blockIdx.x, tid = threadIdx.x;
  int w = tid >> 5, lane = tid & 31;
  const int* ysr = ys + run * NSUP;
  const float* xsr = xs + (size_t)run * NSUP * DIM;
  const float* xqr = xq + (size_t)run * NQ * DIM;

  for (int idx = tid; idx < NQ * WAYS; idx += 160)
    ((float*)P)[idx] = ((const float*)g_P1[run])[idx];
  __syncthreads();

  int extra = g_B1[epoch] - g_b1run[run];
  for (int it = 0; it < extra; it++) {
    if (tid < NQ) {
      float rs = P[tid][0]+P[tid][1]+P[tid][2]+P[tid][3]+P[tid][4];
      float inv = 1.0f / rs;
      #pragma unroll
      for (int k = 0; k < WAYS; k++) P[tid][k] *= inv;
    }
    __syncthreads();
    {
      float part = 0.f;
      for (int i = lane; i < NQ; i += 32) part += P[i][w];
      part = wred(part);
      float f = __shfl_sync(0xffffffffu, 15.0f / part, 0);
      for (int i = lane; i < NQ; i += 32) P[i][w] *= f;
    }
    __syncthreads();
  }

  // Z = [onehot(ys); Pq]
  for (int idx = tid; idx < NF * WAYS; idx += 160) {
    int i = idx / WAYS, k = idx % WAYS;
    float v = (i < NSUP) ? ((ysr[i] == k) ? 1.0f : 0.0f) : P[i - NSUP][k];
    Z[i][k] = v;
  }
  __syncthreads();

  // entropy per row
  if (tid < NF) {
    float p[WAYS], s = 0.f;
    #pragma unroll
    for (int k = 0; k < WAYS; k++) { p[k] = Z[tid][k] + 1e-12f; s += p[k]; }
    float H = 0.f;
    #pragma unroll
    for (int k = 0; k < WAYS; k++) { float q = p[k] / s; H -= q * logf(q); }
    ent[tid] = H / logf(5.0f);
  }
  __syncthreads();

  // Z *= (1 - ent)
  for (int idx = tid; idx < NF * WAYS; idx += 160) {
    int i = idx / WAYS;
    ((float*)Z)[idx] *= (1.0f - ent[i]);
  }
  __syncthreads();
  { // column sums via warp reductions
    float part = 0.f;
    for (int i = lane; i < NF; i += 32) part += Z[i][w];
    part = wred(part);
    if (lane == 0) cs[w] = part;
  }
  __syncthreads();

  // new_proto + blend (threads over d, 4 cols per thread: 4*160=640)
  #pragma unroll
  for (int dd = 0; dd < 4; dd++) {
    int dcol = tid + dd * 160;
    float a[WAYS] = {0.f,0.f,0.f,0.f,0.f};
    for (int i = 0; i < NF; i++) {
      float f = (i < NSUP) ? xsr[i * DIM + dcol] : xqr[(i - NSUP) * DIM + dcol];
      #pragma unroll
      for (int k = 0; k < WAYS; k++) a[k] += Z[i][k] * f;
    }
    #pragma unroll
    for (int k = 0; k < WAYS; k++) {
      float np = a[k] / cs[k];
      float pr = (1.0f - 0.6f) * g_proto[run][k][dcol] + 0.6f * np;
      g_proto[run][k][dcol] = pr;
      psh[k][dcol] = pr;
    }
  }

  if (epoch == 2) {
    __syncthreads();
    { // proto norms, warp w -> class w
      float a = 0.f;
      for (int d = lane; d < DIM; d += 32) { float v = psh[w][d]; a += v * v; }
      a = wred(a);
      if (lane == 0) pn2[w] = a;
    }
    __syncthreads();
    for (int p = w; p < WAYS * WAYS; p += 5) {
      int ia = p / WAYS, ib = p % WAYS;
      float acc = 0.f;
      for (int d = lane; d < DIM; d += 32) acc += psh[ia][d] * psh[ib][d];
      acc = wred(acc);
      if (lane == 0) {
        float d2 = fmaxf(pn2[ia] + pn2[ib] - 2.0f * acc, 0.0f);
        dp[ia][ib] = expf(-LAM * d2);
      }
    }
    __syncthreads();
    if (tid < WAYS) {
      float p[WAYS], s = 0.f;
      #pragma unroll
      for (int k = 0; k < WAYS; k++) { p[k] = dp[tid][k] + 1e-12f; s += p[k]; }
      float H = 0.f;
      #pragma unroll
      for (int k = 0; k < WAYS; k++) { float q = p[k] / s; H -= q * logf(q); }
      score[tid] = H / logf(5.0f);
    }
    if (w == 0) { // omega = mean(ent) via warp 0
      float part = 0.f;
      for (int i = lane; i < NF; i += 32) part += ent[i];
      part = wred(part);
      if (lane == 0) omega_s = part / 100.0f;
    }
    __syncthreads();
    if (tid < WAYS) maskv[tid] = (score[tid] < omega_s) ? 1.0f : 0.0f;
    __syncthreads();
    for (int idx = tid; idx < WAYS * DIM; idx += 160) {
      int k = idx / DIM, d = idx % DIM;
      g_Fp[run][k][d] = psh[k][d] * maskv[k];
    }
    for (int idx = tid; idx < NF * WAYS; idx += 160) {
      int i = idx / WAYS, k = idx % WAYS;
      g_Zext[run][i][k] = Z[i][k];
    }
    if (tid < WAYS * WAYS) {
      int ia = tid / WAYS, k = tid % WAYS;
      g_Zext[run][NF + ia][k] = dp[ia][k] * maskv[ia];
    }
  }
}

// ---------------- KC: Gram + graph + register Cholesky + solves + sinkhorn2
#define FROWS 112
#define KCHUNK 32
#define FPAD 33
#define KC_SMEM (NTOT * NTOT * 4)   // 44,100B (>= FROWS*FPAD*4 = 14,784B)

__global__ __launch_bounds__(256, 2) void kc_kernel(const float* __restrict__ xs,
                                                    const float* __restrict__ xq,
                                                    const int* __restrict__ ys) {
  extern __shared__ float sm[];
  float* Fsh = sm;                  // during Gram
  float* Lsh = sm;                  // after Cholesky (L, lower triangle)
  __shared__ float n2[FROWS];
  __shared__ float rsum[FROWS];
  __shared__ float Dm[FROWS];
  __shared__ float colbuf[2][FROWS];
  __shared__ float sh_piv;
  __shared__ float yv[NTOT][WAYS];
  __shared__ float u2[NTOT];
  __shared__ int sdelta;

  int run = blockIdx.x, tid = threadIdx.x;
  int ti = tid >> 4, tj = tid & 15;
  int w = tid >> 5, lane = tid & 31;
  const float* xsr = xs + (size_t)run * NSUP * DIM;
  const float* xqr = xq + (size_t)run * NQ * DIM;
  const int* ysr = ys + run * NSUP;

  float acc[7][7];
  #pragma unroll
  for (int r = 0; r < 7; r++)
    #pragma unroll
    for (int c = 0; c < 7; c++) acc[r][c] = 0.f;

  // ---- Gram: acc = F F^T tile (ti,tj) ----
  for (int c0 = 0; c0 < DIM; c0 += KCHUNK) {
    __syncthreads();
    for (int e = tid; e < FROWS * KCHUNK; e += 256) {
      int r = e >> 5, dd = e & 31;
      float v = 0.f;
      if (r < NSUP)       v = xsr[r * DIM + c0 + dd];
      else if (r < NF)    v = xqr[(r - NSUP) * DIM + c0 + dd];
      else if (r < NTOT)  v = g_Fp[run][r - NF][c0 + dd];
      Fsh[r * FPAD + dd] = v;
    }
    __syncthreads();
    for (int dd = 0; dd < KCHUNK; dd++) {
      float a[7], bv[7];
      #pragma unroll
      for (int r = 0; r < 7; r++) a[r] = Fsh[(ti * 7 + r) * FPAD + dd];
      #pragma unroll
      for (int c = 0; c < 7; c++) bv[c] = Fsh[(tj * 7 + c) * FPAD + dd];
      #pragma unroll
      for (int r = 0; r < 7; r++)
        #pragma unroll
        for (int c = 0; c < 7; c++) acc[r][c] += a[r] * bv[c];
    }
  }
  __syncthreads();

  // ---- diag norms ----
  if (ti == tj) {
    #pragma unroll
    for (int r = 0; r < 7; r++) n2[ti * 7 + r] = acc[r][r];
  }
  if (tid < FROWS) rsum[tid] = 0.f;
  __syncthreads();

  // ---- W = exp(-LAM*d2), zero diag, zero out-of-range ----
  #pragma unroll
  for (int r = 0; r < 7; r++) {
    int gi = ti * 7 + r;
    #pragma unroll
    for (int c = 0; c < 7; c++) {
      int gj = tj * 7 + c;
      float wv = 0.f;
      if (gi < NTOT && gj < NTOT && gi != gj) {
        float d2 = fmaxf(n2[gi] + n2[gj] - 2.0f * acc[r][c], 0.0f);
        wv = expf(-LAM * d2);
      }
      acc[r][c] = wv;
    }
  }
  // ---- row sums ----
  #pragma unroll
  for (int r = 0; r < 7; r++) {
    float p = 0.f;
    #pragma unroll
    for (int c = 0; c < 7; c++) p += acc[r][c];
    atomicAdd(&rsum[ti * 7 + r], p);
  }
  __syncthreads();
  if (tid < FROWS) Dm[tid] = (tid < NTOT) ? (1.0f / sqrtf(rsum[tid])) : 0.f;
  __syncthreads();

  // ---- A = I - ALPHA * Dm_i W Dm_j (in registers) ----
  #pragma unroll
  for (int r = 0; r < 7; r++) {
    int gi = ti * 7 + r;
    float di = Dm[gi];
    #pragma unroll
    for (int c = 0; c < 7; c++) {
      int gj = tj * 7 + c;
      acc[r][c] = ((gi == gj) ? 1.0f : 0.0f) - ALPHA_ * di * acc[r][c] * Dm[gj];
    }
  }
  __syncthreads();

  // ---- register-resident Cholesky, rank-1 updates via shared column bcast --
  for (int jt = 0; jt < 15; jt++) {
    #pragma unroll
    for (int jc = 0; jc < 7; jc++) {
      int j = jt * 7 + jc;
      int buf = j & 1;
      if (tid < FROWS) colbuf[buf][tid] = 0.f;
      if (ti == jt && tj == jt) {
        float pv = sqrtf(acc[jc][jc]);
        acc[jc][jc] = pv;
        sh_piv = pv;
      }
      __syncthreads();
      if (tj == jt) {
        float ip = 1.0f / sh_piv;
        #pragma unroll
        for (int r = 0; r < 7; r++) {
          int gi = ti * 7 + r;
          if (gi > j) { acc[r][jc] *= ip; colbuf[buf][gi] = acc[r][jc]; }
        }
      }
      __syncthreads();
      float rv[7], cv[7];
      #pragma unroll
      for (int r = 0; r < 7; r++) rv[r] = colbuf[buf][ti * 7 + r];
      #pragma unroll
      for (int c = 0; c < 7; c++) cv[c] = colbuf[buf][tj * 7 + c];
      #pragma unroll
      for (int r = 0; r < 7; r++)
        #pragma unroll
        for (int c = 0; c < 7; c++) acc[r][c] -= rv[r] * cv[c];
    }
  }
  __syncthreads();   // Fsh region dead; reuse as Lsh

  // ---- dump L (lower + diag) to shared ----
  #pragma unroll
  for (int r = 0; r < 7; r++) {
    int gi = ti * 7 + r;
    #pragma unroll
    for (int c = 0; c < 7; c++) {
      int gj = tj * 7 + c;
      if (gi < NTOT && gj < NTOT && gj <= gi) Lsh[gi * NTOT + gj] = acc[r][c];
    }
  }
  for (int idx = tid; idx < NTOT * WAYS; idx += 256)
    ((float*)yv)[idx] = ((const float*)g_Zext[run])[idx];
  __syncthreads();

  // ---- triangular solves: warp w handles RHS column w ----
  if (w < WAYS) {
    // forward: L y = b
    for (int i = 0; i < NTOT; i++) {
      float part = 0.f;
      for (int jj = lane; jj < i; jj += 32) part += Lsh[i * NTOT + jj] * yv[jj][w];
      part = wred(part);
      if (lane == 0) yv[i][w] = (yv[i][w] - part) / Lsh[i * NTOT + i];
      __syncwarp();
    }
    // backward: L^T x = y
    for (int i = NTOT - 1; i >= 0; i--) {
      float part = 0.f;
      for (int jj = i + 1 + lane; jj < NTOT; jj += 32) part += Lsh[jj * NTOT + i] * yv[jj][w];
      part = wred(part);
      if (lane == 0) yv[i][w] = (yv[i][w] - part) / Lsh[i * NTOT + i];
      __syncwarp();
    }
  }
  if (tid < NTOT) u2[tid] = 0.f;
  __syncthreads();

  // ---- sinkhorn2 pass-1 (n=105, c=21, n_l=25), warp-parallel columns ----
  int b = 0;
  for (;;) {
    if (tid == 0) sdelta = 0;
    __syncthreads();
    float rs = 0.f;
    if (tid < NTOT) {
      rs = yv[tid][0]+yv[tid][1]+yv[tid][2]+yv[tid][3]+yv[tid][4];
      atomicMax(&sdelta, __float_as_int(fabsf(u2[tid] - rs)));
    }
    __syncthreads();
    float delta = __int_as_float(sdelta);
    if (!(delta > EPSV && b < MAXIT)) break;
    if (tid < NTOT) {
      u2[tid] = rs;
      float inv = 1.0f / rs;
      #pragma unroll
      for (int k = 0; k < WAYS; k++) yv[tid][k] *= inv;
    }
    __syncthreads();
    if (w < WAYS) {
      float part = 0.f;
      for (int i = lane; i < NTOT; i += 32) part += yv[i][w];
      part = wred(part);
      float f = __shfl_sync(0xffffffffu, 21.0f / part, 0);
      for (int i = lane; i < NTOT; i += 32) yv[i][w] *= f;
    }
    __syncthreads();
    if (tid < NSUP) {
      int cls = ysr[tid];
      #pragma unroll
      for (int k = 0; k < WAYS; k++) yv[tid][k] = (k == cls) ? 1.0f : 0.0f;
    }
    __syncthreads();
    b++;
  }
  if (tid == 0) { atomicMax(&g_B2, b); g_b2run[run] = b; }
  for (int idx = tid; idx < NTOT * WAYS; idx += 256)
    ((float*)g_Z0[run])[idx] = ((float*)yv)[idx];
}

// ---------------- KD: continue sinkhorn2, argmax, accuracy -----------------
__global__ __launch_bounds__(160) void kd_kernel(const int* __restrict__ ys,
                                                 const int* __restrict__ yq,
                                                 float* __restrict__ out) {
  __shared__ float P[NTOT][WAYS];
  __shared__ int cnt;
  int run = blockIdx.x, tid = threadIdx.x;
  int w = tid >> 5, lane = tid & 31;
  const int* ysr = ys + run * NSUP;
  for (int idx = tid; idx < NTOT * WAYS; idx += 160)
    ((float*)P)[idx] = ((const float*)g_Z0[run])[idx];
  __syncthreads();
  int extra = g_B2 - g_b2run[run];
  for (int it = 0; it < extra; it++) {
    if (tid < NTOT) {
      float rs = P[tid][0]+P[tid][1]+P[tid][2]+P[tid][3]+P[tid][4];
      float inv = 1.0f / rs;
      #pragma unroll
      for (int k = 0; k < WAYS; k++) P[tid][k] *= inv;
    }
    __syncthreads();
    {
      float part = 0.f;
      for (int i = lane; i < NTOT; i += 32) part += P[i][w];
      part = wred(part);
      float f = __shfl_sync(0xffffffffu, 21.0f / part, 0);
      for (int i = lane; i < NTOT; i += 32) P[i][w] *= f;
    }
    __syncthreads();
    if (tid < NSUP) {
      int cls = ysr[tid];
      #pragma unroll
      for (int k = 0; k < WAYS; k++) P[tid][k] = (k == cls) ? 1.0f : 0.0f;
    }
    __syncthreads();
  }
  if (tid == 0) cnt = 0;
  __syncthreads();
  if (tid < NQ) {
    int i = NSUP + tid;
    float best = P[i][0]; int bi = 0;
    #pragma unroll
    for (int k = 1; k < WAYS; k++)
      if (P[i][k] > best) { best = P[i][k]; bi = k; }
    if (bi == yq[run * NQ + tid]) atomicAdd(&cnt, 1);
  }
  __syncthreads();
  if (tid == 0) out[run] = (float)cnt / 75.0f;
}

// ---------------------------------------------------------------------------
extern "C" void kernel_launch(void* const* d_in, const int* in_sizes, int n_in,
                              void* d_out, int out_size) {
  const float* xs = (const float*)d_in[0];
  const float* xq = (const float*)d_in[1];
  const int*   ys = (const int*)d_in[2];
  const int*   yq = (const int*)d_in[3];
  float* out = (float*)d_out;

  cudaFuncSetAttribute(kc_kernel, cudaFuncAttributeMaxDynamicSharedMemorySize,
                       KC_SMEM);

  kzero_kernel<<<1, 32>>>();
  for (int e = 0; e < 3; e++) {
    ka_kernel<<<RUNS, 160>>>(xs, xq, e);
    kb_kernel<<<RUNS, 160>>>(xs, xq, ys, e);
  }
  kc_kernel<<<RUNS, 256, KC_SMEM>>>(xs, xq, ys);
  kd_kernel<<<RUNS, 160>>>(ys, yq, out);
}

// round 6
// speedup vs baseline: 1.3738x; 1.3521x over previous
#include <cuda_runtime.h>
#include <math.h>
#include <stdint.h>

#define RUNS 512
#define WAYS 5
#define SHOT 5
#define NSUP 25
#define NQ   75
#define NF   100
#define NTOT 105
#define DIM  640
#define LAM  10.0f
#define ALPHA_ 0.7f
#define EPSV 1e-3f
#define MAXIT 1000

// ---------------- device scratch (static: no allocations allowed) ----------
__device__ float g_proto[RUNS][WAYS][DIM];
__device__ float g_Fp[RUNS][WAYS][DIM];     // masked proto rows (epoch 2)
__device__ float g_P1[RUNS][NQ][WAYS];      // sinkhorn1 state after pass-1
__device__ int   g_b1run[RUNS];             // per-run pass-1 body count
__device__ float g_Zext[RUNS][NTOT][WAYS];  // extended Z (epoch 2, pre-solve)
__device__ float g_Z0[RUNS][NTOT][WAYS];    // sinkhorn2 state after pass-1
__device__ int   g_b2run[RUNS];

__device__ __forceinline__ float wred(float v) {
  #pragma unroll
  for (int o = 16; o; o >>= 1) v += __shfl_down_sync(0xffffffffu, v, o);
  return v;
}
__device__ __forceinline__ float wsum_x(float v) {
  #pragma unroll
  for (int o = 16; o; o >>= 1) v += __shfl_xor_sync(0xffffffffu, v, o);
  return v;
}
__device__ __forceinline__ float wmax_x(float v) {
  #pragma unroll
  for (int o = 16; o; o >>= 1) v = fmaxf(v, __shfl_xor_sync(0xffffffffu, v, o));
  return v;
}

// ---- single-warp register sinkhorn: pass-1 (count bodies to own converge) --
template<int NR, int NROWS, bool LAB>
__device__ __forceinline__ int sink_pass1(float (&P)[NR][WAYS], float ctot,
                                          int lane, int cls) {
  float u[NR];
  #pragma unroll
  for (int s = 0; s < NR; s++) u[s] = 0.f;
  int b = 0;
  for (;;) {
    float rs[NR];
    float d = 0.f;
    #pragma unroll
    for (int s = 0; s < NR; s++) {
      rs[s] = P[s][0] + P[s][1] + P[s][2] + P[s][3] + P[s][4];
      if (lane + 32 * s < NROWS) d = fmaxf(d, fabsf(u[s] - rs[s]));
    }
    float delta = wmax_x(d);           // overlaps with speculative body below
    // --- speculative body (commit only if continuing) ---
    float t[NR][WAYS];
    float cp[WAYS] = {0.f, 0.f, 0.f, 0.f, 0.f};
    #pragma unroll
    for (int s = 0; s < NR; s++) {
      float inv = (lane + 32 * s < NROWS) ? (1.0f / rs[s]) : 0.f;
      #pragma unroll
      for (int k = 0; k < WAYS; k++) { t[s][k] = P[s][k] * inv; cp[k] += t[s][k]; }
    }
    float f[WAYS];
    #pragma unroll
    for (int k = 0; k < WAYS; k++) f[k] = ctot / wsum_x(cp[k]);
    #pragma unroll
    for (int s = 0; s < NR; s++)
      #pragma unroll
      for (int k = 0; k < WAYS; k++) t[s][k] *= f[k];
    if (LAB && lane < NSUP) {
      #pragma unroll
      for (int k = 0; k < WAYS; k++) t[0][k] = (k == cls) ? 1.f : 0.f;
    }
    if (!(delta > EPSV && b < MAXIT)) break;
    #pragma unroll
    for (int s = 0; s < NR; s++) {
      u[s] = rs[s];
      #pragma unroll
      for (int k = 0; k < WAYS; k++) P[s][k] = t[s][k];
    }
    b++;
  }
  return b;
}

// ---- single-warp register sinkhorn: replay exactly `iters` bodies ----------
template<int NR, int NROWS, bool LAB>
__device__ __forceinline__ void sink_replay(float (&P)[NR][WAYS], float ctot,
                                            int lane, int cls, int iters) {
  for (int it = 0; it < iters; it++) {
    float cp[WAYS] = {0.f, 0.f, 0.f, 0.f, 0.f};
    #pragma unroll
    for (int s = 0; s < NR; s++) {
      float rs = P[s][0] + P[s][1] + P[s][2] + P[s][3] + P[s][4];
      float inv = (lane + 32 * s < NROWS) ? (1.0f / rs) : 0.f;
      #pragma unroll
      for (int k = 0; k < WAYS; k++) { P[s][k] *= inv; cp[k] += P[s][k]; }
    }
    float f[WAYS];
    #pragma unroll
    for (int k = 0; k < WAYS; k++) f[k] = ctot / wsum_x(cp[k]);
    #pragma unroll
    for (int s = 0; s < NR; s++)
      #pragma unroll
      for (int k = 0; k < WAYS; k++) P[s][k] *= f[k];
    if (LAB && lane < NSUP) {
      #pragma unroll
      for (int k = 0; k < WAYS; k++) P[0][k] = (k == cls) ? 1.f : 0.f;
    }
  }
}

// ---------------- KA: proto load, Pq0, sinkhorn1 pass-1 (save state) -------
__global__ __launch_bounds__(160) void ka_kernel(const float* __restrict__ xs,
                                                 const float* __restrict__ xq,
                                                 int epoch) {
  __shared__ float ps[WAYS][DIM];
  __shared__ float pn[WAYS];
  __shared__ float Psh[NQ][WAYS];
  int run = blockIdx.x;
  int tid = threadIdx.x, w = tid >> 5, lane = tid & 31;
  const float* xsr = xs + (size_t)run * NSUP * DIM;
  const float* xqr = xq + (size_t)run * NQ * DIM;

  if (epoch == 0) {
    for (int idx = tid; idx < WAYS * DIM; idx += 160) {
      int k = idx / DIM, d = idx % DIM;
      float s = 0.f;
      #pragma unroll
      for (int sh = 0; sh < SHOT; sh++) s += xsr[(k * SHOT + sh) * DIM + d];
      float v = s / 5.0f;
      ps[k][d] = v;
      g_proto[run][k][d] = v;
    }
  } else {
    for (int idx = tid; idx < WAYS * DIM; idx += 160) {
      int k = idx / DIM, d = idx % DIM;
      ps[k][d] = g_proto[run][k][d];
    }
  }
  __syncthreads();

  { // proto norms (warp w does class w)
    float a = 0.f;
    for (int d = lane; d < DIM; d += 32) { float v = ps[w][d]; a += v * v; }
    a = wred(a);
    if (lane == 0) pn[w] = a;
  }
  __syncthreads();

  // Pq = exp(-LAM * d2(query, proto))
  for (int q = w; q < NQ; q += 5) {
    float a0=0,a1=0,a2=0,a3=0,a4=0,an=0;
    const float* xr = xqr + q * DIM;
    #pragma unroll 4
    for (int d = lane; d < DIM; d += 32) {
      float x = xr[d];
      an += x*x;
      a0 += x*ps[0][d]; a1 += x*ps[1][d]; a2 += x*ps[2][d];
      a3 += x*ps[3][d]; a4 += x*ps[4][d];
    }
    an = wred(an); a0 = wred(a0); a1 = wred(a1); a2 = wred(a2); a3 = wred(a3); a4 = wred(a4);
    if (lane == 0) {
      float acc[5] = {a0,a1,a2,a3,a4};
      #pragma unroll
      for (int k = 0; k < WAYS; k++) {
        float d2 = fmaxf(an + pn[k] - 2.0f * acc[k], 0.0f);
        Psh[q][k] = expf(-LAM * d2);
      }
    }
  }
  __syncthreads();

  // warp 0: register sinkhorn pass-1, save state + per-run body count
  if (tid < 32) {
    float P[3][WAYS];
    #pragma unroll
    for (int s = 0; s < 3; s++) {
      int row = lane + 32 * s;
      #pragma unroll
      for (int k = 0; k < WAYS; k++) P[s][k] = (row < NQ) ? Psh[row][k] : 0.f;
    }
    int b = sink_pass1<3, NQ, false>(P, 15.0f, lane, 0);
    #pragma unroll
    for (int s = 0; s < 3; s++) {
      int row = lane + 32 * s;
      if (row < NQ)
        #pragma unroll
        for (int k = 0; k < WAYS; k++) g_P1[run][row][k] = P[s][k];
    }
    if (lane == 0) g_b1run[run] = b;
  }
}

// ---------------- KB: continue sinkhorn1, entropy, proto blend; epoch2 tail
__global__ __launch_bounds__(160) void kb_kernel(const float* __restrict__ xs,
                                                 const float* __restrict__ xq,
                                                 const int* __restrict__ ys,
                                                 int epoch) {
  __shared__ float Psh[NQ][WAYS];
  __shared__ float Z[NF][WAYS];
  __shared__ float ent[NF];
  __shared__ float cs[WAYS];
  __shared__ float psh[WAYS][DIM];
  __shared__ float pn2[WAYS];
  __shared__ float dp[WAYS][WAYS];
  __shared__ float score[WAYS], maskv[WAYS];
  __shared__ float omega_s;
  int run = blockIdx.x, tid = threadIdx.x;
  int w = tid >> 5, lane = tid & 31;
  const int* ysr = ys + run * NSUP;
  const float* xsr = xs + (size_t)run * NSUP * DIM;
  const float* xqr = xq + (size_t)run * NQ * DIM;

  if (tid < 32) {  // warp 0: replay to global B1, registers only
    float P[3][WAYS];
    #pragma unroll
    for (int s = 0; s < 3; s++) {
      int row = lane + 32 * s;
      #pragma unroll
      for (int k = 0; k < WAYS; k++) P[s][k] = (row < NQ) ? g_P1[run][row][k] : 0.f;
    }
    int m = 0;
    for (int i = lane; i < RUNS; i += 32) m = max(m, g_b1run[i]);
    m = __reduce_max_sync(0xffffffffu, m);
    int extra = m - g_b1run[run];
    sink_replay<3, NQ, false>(P, 15.0f, lane, 0, extra);
    #pragma unroll
    for (int s = 0; s < 3; s++) {
      int row = lane + 32 * s;
      if (row < NQ)
        #pragma unroll
        for (int k = 0; k < WAYS; k++) Psh[row][k] = P[s][k];
    }
  }
  __syncthreads();

  // Z = [onehot(ys); Pq]
  for (int idx = tid; idx < NF * WAYS; idx += 160) {
    int i = idx / WAYS, k = idx % WAYS;
    float v = (i < NSUP) ? ((ysr[i] == k) ? 1.0f : 0.0f) : Psh[i - NSUP][k];
    Z[i][k] = v;
  }
  __syncthreads();

  // entropy per row
  if (tid < NF) {
    float p[WAYS], s = 0.f;
    #pragma unroll
    for (int k = 0; k < WAYS; k++) { p[k] = Z[tid][k] + 1e-12f; s += p[k]; }
    float H = 0.f;
    #pragma unroll
    for (int k = 0; k < WAYS; k++) { float q = p[k] / s; H -= q * logf(q); }
    ent[tid] = H / logf(5.0f);
  }
  __syncthreads();

  // Z *= (1 - ent)
  for (int idx = tid; idx < NF * WAYS; idx += 160) {
    int i = idx / WAYS;
    ((float*)Z)[idx] *= (1.0f - ent[i]);
  }
  __syncthreads();
  { // column sums via warp reductions (warp w -> class w)
    float part = 0.f;
    for (int i = lane; i < NF; i += 32) part += Z[i][w];
    part = wred(part);
    if (lane == 0) cs[w] = part;
  }
  __syncthreads();

  // new_proto + blend (threads over d, 4 cols per thread: 4*160=640)
  #pragma unroll
  for (int dd = 0; dd < 4; dd++) {
    int dcol = tid + dd * 160;
    float a[WAYS] = {0.f,0.f,0.f,0.f,0.f};
    for (int i = 0; i < NF; i++) {
      float f = (i < NSUP) ? xsr[i * DIM + dcol] : xqr[(i - NSUP) * DIM + dcol];
      #pragma unroll
      for (int k = 0; k < WAYS; k++) a[k] += Z[i][k] * f;
    }
    #pragma unroll
    for (int k = 0; k < WAYS; k++) {
      float np = a[k] / cs[k];
      float pr = (1.0f - 0.6f) * g_proto[run][k][dcol] + 0.6f * np;
      g_proto[run][k][dcol] = pr;
      psh[k][dcol] = pr;
    }
  }

  if (epoch == 2) {
    __syncthreads();
    { // proto norms, warp w -> class w
      float a = 0.f;
      for (int d = lane; d < DIM; d += 32) { float v = psh[w][d]; a += v * v; }
      a = wred(a);
      if (lane == 0) pn2[w] = a;
    }
    __syncthreads();
    for (int p = w; p < WAYS * WAYS; p += 5) {
      int ia = p / WAYS, ib = p % WAYS;
      float acc = 0.f;
      for (int d = lane; d < DIM; d += 32) acc += psh[ia][d] * psh[ib][d];
      acc = wred(acc);
      if (lane == 0) {
        float d2 = fmaxf(pn2[ia] + pn2[ib] - 2.0f * acc, 0.0f);
        dp[ia][ib] = expf(-LAM * d2);
      }
    }
    __syncthreads();
    if (tid < WAYS) {
      float p[WAYS], s = 0.f;
      #pragma unroll
      for (int k = 0; k < WAYS; k++) { p[k] = dp[tid][k] + 1e-12f; s += p[k]; }
      float H = 0.f;
      #pragma unroll
      for (int k = 0; k < WAYS; k++) { float q = p[k] / s; H -= q * logf(q); }
      score[tid] = H / logf(5.0f);
    }
    if (w == 0) { // omega = mean(ent)
      float part = 0.f;
      for (int i = lane; i < NF; i += 32) part += ent[i];
      part = wred(part);
      if (lane == 0) omega_s = part / 100.0f;
    }
    __syncthreads();
    if (tid < WAYS) maskv[tid] = (score[tid] < omega_s) ? 1.0f : 0.0f;
    __syncthreads();
    for (int idx = tid; idx < WAYS * DIM; idx += 160) {
      int k = idx / DIM, d = idx % DIM;
      g_Fp[run][k][d] = psh[k][d] * maskv[k];
    }
    for (int idx = tid; idx < NF * WAYS; idx += 160) {
      int i = idx / WAYS, k = idx % WAYS;
      g_Zext[run][i][k] = Z[i][k];
    }
    if (tid < WAYS * WAYS) {
      int ia = tid / WAYS, k = tid % WAYS;
      g_Zext[run][NF + ia][k] = dp[ia][k] * maskv[ia];
    }
  }
}

// ---------------- KC: Gram + graph + register Cholesky + solves + sinkhorn2
#define FROWS 112
#define KCHUNK 32
#define FPAD 33
#define KC_SMEM (NTOT * NTOT * 4)   // 44,100B (>= FROWS*FPAD*4 = 14,784B)

__global__ __launch_bounds__(256, 2) void kc_kernel(const float* __restrict__ xs,
                                                    const float* __restrict__ xq,
                                                    const int* __restrict__ ys) {
  extern __shared__ float sm[];
  float* Fsh = sm;                  // during Gram
  float* Lsh = sm;                  // after Cholesky (L, lower triangle)
  __shared__ float n2[FROWS];
  __shared__ float rsum[FROWS];
  __shared__ float Dm[FROWS];
  __shared__ float colbuf[2][FROWS];
  __shared__ float sh_piv;
  __shared__ float yv[NTOT][WAYS];

  int run = blockIdx.x, tid = threadIdx.x;
  int ti = tid >> 4, tj = tid & 15;
  int w = tid >> 5, lane = tid & 31;
  const float* xsr = xs + (size_t)run * NSUP * DIM;
  const float* xqr = xq + (size_t)run * NQ * DIM;
  const int* ysr = ys + run * NSUP;

  float acc[7][7];
  #pragma unroll
  for (int r = 0; r < 7; r++)
    #pragma unroll
    for (int c = 0; c < 7; c++) acc[r][c] = 0.f;

  // ---- Gram: acc = F F^T tile (ti,tj) ----
  for (int c0 = 0; c0 < DIM; c0 += KCHUNK) {
    __syncthreads();
    for (int e = tid; e < FROWS * KCHUNK; e += 256) {
      int r = e >> 5, dd = e & 31;
      float v = 0.f;
      if (r < NSUP)       v = xsr[r * DIM + c0 + dd];
      else if (r < NF)    v = xqr[(r - NSUP) * DIM + c0 + dd];
      else if (r < NTOT)  v = g_Fp[run][r - NF][c0 + dd];
      Fsh[r * FPAD + dd] = v;
    }
    __syncthreads();
    for (int dd = 0; dd < KCHUNK; dd++) {
      float a[7], bv[7];
      #pragma unroll
      for (int r = 0; r < 7; r++) a[r] = Fsh[(ti * 7 + r) * FPAD + dd];
      #pragma unroll
      for (int c = 0; c < 7; c++) bv[c] = Fsh[(tj * 7 + c) * FPAD + dd];
      #pragma unroll
      for (int r = 0; r < 7; r++)
        #pragma unroll
        for (int c = 0; c < 7; c++) acc[r][c] += a[r] * bv[c];
    }
  }
  __syncthreads();

  // ---- diag norms ----
  if (ti == tj) {
    #pragma unroll
    for (int r = 0; r < 7; r++) n2[ti * 7 + r] = acc[r][r];
  }
  if (tid < FROWS) rsum[tid] = 0.f;
  __syncthreads();

  // ---- W = exp(-LAM*d2), zero diag, zero out-of-range ----
  #pragma unroll
  for (int r = 0; r < 7; r++) {
    int gi = ti * 7 + r;
    #pragma unroll
    for (int c = 0; c < 7; c++) {
      int gj = tj * 7 + c;
      float wv = 0.f;
      if (gi < NTOT && gj < NTOT && gi != gj) {
        float d2 = fmaxf(n2[gi] + n2[gj] - 2.0f * acc[r][c], 0.0f);
        wv = expf(-LAM * d2);
      }
      acc[r][c] = wv;
    }
  }
  // ---- row sums ----
  #pragma unroll
  for (int r = 0; r < 7; r++) {
    float p = 0.f;
    #pragma unroll
    for (int c = 0; c < 7; c++) p += acc[r][c];
    atomicAdd(&rsum[ti * 7 + r], p);
  }
  __syncthreads();
  if (tid < FROWS) Dm[tid] = (tid < NTOT) ? (1.0f / sqrtf(rsum[tid])) : 0.f;
  __syncthreads();

  // ---- A = I - ALPHA * Dm_i W Dm_j (in registers) ----
  #pragma unroll
  for (int r = 0; r < 7; r++) {
    int gi = ti * 7 + r;
    float di = Dm[gi];
    #pragma unroll
    for (int c = 0; c < 7; c++) {
      int gj = tj * 7 + c;
      acc[r][c] = ((gi == gj) ? 1.0f : 0.0f) - ALPHA_ * di * acc[r][c] * Dm[gj];
    }
  }
  __syncthreads();

  // ---- register-resident Cholesky, rank-1 updates via shared column bcast --
  for (int jt = 0; jt < 15; jt++) {
    #pragma unroll
    for (int jc = 0; jc < 7; jc++) {
      int j = jt * 7 + jc;
      int buf = j & 1;
      if (tid < FROWS) colbuf[buf][tid] = 0.f;
      if (ti == jt && tj == jt) {
        float pv = sqrtf(acc[jc][jc]);
        acc[jc][jc] = pv;
        sh_piv = pv;
      }
      __syncthreads();
      if (tj == jt) {
        float ip = 1.0f / sh_piv;
        #pragma unroll
        for (int r = 0; r < 7; r++) {
          int gi = ti * 7 + r;
          if (gi > j) { acc[r][jc] *= ip; colbuf[buf][gi] = acc[r][jc]; }
        }
      }
      __syncthreads();
      float rv[7], cv[7];
      #pragma unroll
      for (int r = 0; r < 7; r++) rv[r] = colbuf[buf][ti * 7 + r];
      #pragma unroll
      for (int c = 0; c < 7; c++) cv[c] = colbuf[buf][tj * 7 + c];
      #pragma unroll
      for (int r = 0; r < 7; r++)
        #pragma unroll
        for (int c = 0; c < 7; c++) acc[r][c] -= rv[r] * cv[c];
    }
  }
  __syncthreads();   // Fsh region dead; reuse as Lsh

  // ---- dump L (lower + diag) to shared ----
  #pragma unroll
  for (int r = 0; r < 7; r++) {
    int gi = ti * 7 + r;
    #pragma unroll
    for (int c = 0; c < 7; c++) {
      int gj = tj * 7 + c;
      if (gi < NTOT && gj < NTOT && gj <= gi) Lsh[gi * NTOT + gj] = acc[r][c];
    }
  }
  for (int idx = tid; idx < NTOT * WAYS; idx += 256)
    ((float*)yv)[idx] = ((const float*)g_Zext[run])[idx];
  __syncthreads();

  // ---- triangular solves: warp w handles RHS column w ----
  if (w < WAYS) {
    // forward: L y = b
    for (int i = 0; i < NTOT; i++) {
      float part = 0.f;
      for (int jj = lane; jj < i; jj += 32) part += Lsh[i * NTOT + jj] * yv[jj][w];
      part = wred(part);
      if (lane == 0) yv[i][w] = (yv[i][w] - part) / Lsh[i * NTOT + i];
      __syncwarp();
    }
    // backward: L^T x = y
    for (int i = NTOT - 1; i >= 0; i--) {
      float part = 0.f;
      for (int jj = i + 1 + lane; jj < NTOT; jj += 32) part += Lsh[jj * NTOT + i] * yv[jj][w];
      part = wred(part);
      if (lane == 0) yv[i][w] = (yv[i][w] - part) / Lsh[i * NTOT + i];
      __syncwarp();
    }
  }
  __syncthreads();

  // ---- sinkhorn2 pass-1: warp 0, registers ----
  if (tid < 32) {
    float P[4][WAYS];
    #pragma unroll
    for (int s = 0; s < 4; s++) {
      int row = lane + 32 * s;
      #pragma unroll
      for (int k = 0; k < WAYS; k++) P[s][k] = (row < NTOT) ? yv[row][k] : 0.f;
    }
    int cls = (lane < NSUP) ? ysr[lane] : 0;
    int b = sink_pass1<4, NTOT, true>(P, 21.0f, lane, cls);
    #pragma unroll
    for (int s = 0; s < 4; s++) {
      int row = lane + 32 * s;
      if (row < NTOT)
        #pragma unroll
        for (int k = 0; k < WAYS; k++) g_Z0[run][row][k] = P[s][k];
    }
    if (lane == 0) g_b2run[run] = b;
  }
}

// ---------------- KD: 1 warp per run: replay sinkhorn2, argmax, accuracy ----
__global__ __launch_bounds__(128) void kd_kernel(const int* __restrict__ ys,
                                                 const int* __restrict__ yq,
                                                 float* __restrict__ out) {
  int tid = threadIdx.x, w = tid >> 5, lane = tid & 31;
  int run = blockIdx.x * 4 + w;
  const int* ysr = ys + run * NSUP;
  float P[4][WAYS];
  #pragma unroll
  for (int s = 0; s < 4; s++) {
    int row = lane + 32 * s;
    #pragma unroll
    for (int k = 0; k < WAYS; k++) P[s][k] = (row < NTOT) ? g_Z0[run][row][k] : 0.f;
  }
  int cls = (lane < NSUP) ? ysr[lane] : 0;
  int m = 0;
  for (int i = lane; i < RUNS; i += 32) m = max(m, g_b2run[i]);
  m = __reduce_max_sync(0xffffffffu, m);
  int extra = m - g_b2run[run];
  sink_replay<4, NTOT, true>(P, 21.0f, lane, cls, extra);

  int cnt = 0;
  #pragma unroll
  for (int s = 0; s < 4; s++) {
    int row = lane + 32 * s;
    if (row >= NSUP && row < NF) {
      float best = P[s][0]; int bi = 0;
      #pragma unroll
      for (int k = 1; k < WAYS; k++)
        if (P[s][k] > best) { best = P[s][k]; bi = k; }
      if (bi == yq[run * NQ + (row - NSUP)]) cnt++;
    }
  }
  #pragma unroll
  for (int o = 16; o; o >>= 1) cnt += __shfl_xor_sync(0xffffffffu, cnt, o);
  if (lane == 0) out[run] = (float)cnt / 75.0f;
}

// ---------------------------------------------------------------------------
extern "C" void kernel_launch(void* const* d_in, const int* in_sizes, int n_in,
                              void* d_out, int out_size) {
  const float* xs = (const float*)d_in[0];
  const float* xq = (const float*)d_in[1];
  const int*   ys = (const int*)d_in[2];
  const int*   yq = (const int*)d_in[3];
  float* out = (float*)d_out;

  cudaFuncSetAttribute(kc_kernel, cudaFuncAttributeMaxDynamicSharedMemorySize,
                       KC_SMEM);

  for (int e = 0; e < 3; e++) {
    ka_kernel<<<RUNS, 160>>>(xs, xq, e);
    kb_kernel<<<RUNS, 160>>>(xs, xq, ys, e);
  }
  kc_kernel<<<RUNS, 256, KC_SMEM>>>(xs, xq, ys);
  kd_kernel<<<RUNS / 4, 128>>>(ys, yq, out);
}

// round 8
// speedup vs baseline: 1.5719x; 1.1441x over previous
#include <cuda_runtime.h>
#include <math.h>
#include <stdint.h>

#define RUNS 512
#define WAYS 5
#define SHOT 5
#define NSUP 25
#define NQ   75
#define NF   100
#define NTOT 105
#define DIM  640
#define LAM  10.0f
#define ALPHA_ 0.7f
#define EPSV 1e-3f
#define MAXIT 1000

// ---------------- device scratch (static: no allocations allowed) ----------
__device__ float g_proto[RUNS][WAYS][DIM];
__device__ float g_Fp[RUNS][WAYS][DIM];     // masked proto rows (epoch 2)
__device__ float g_P1[RUNS][NQ][WAYS];      // sinkhorn1 state after pass-1
__device__ int   g_b1A[RUNS];               // per-run body counts (double buf)
__device__ int   g_b1B[RUNS];
__device__ float g_Zext[RUNS][NTOT][WAYS];  // extended Z (epoch 2, pre-solve)
__device__ float g_Z0[RUNS][NTOT][WAYS];    // sinkhorn2 state after pass-1
__device__ int   g_b2run[RUNS];

__device__ __forceinline__ float wred(float v) {
  #pragma unroll
  for (int o = 16; o; o >>= 1) v += __shfl_down_sync(0xffffffffu, v, o);
  return v;
}
__device__ __forceinline__ float wsum_x(float v) {
  #pragma unroll
  for (int o = 16; o; o >>= 1) v += __shfl_xor_sync(0xffffffffu, v, o);
  return v;
}
__device__ __forceinline__ float wmax_x(float v) {
  #pragma unroll
  for (int o = 16; o; o >>= 1) v = fmaxf(v, __shfl_xor_sync(0xffffffffu, v, o));
  return v;
}

// ---- single-warp register sinkhorn: pass-1 (count bodies to own converge) --
template<int NR, int NROWS, bool LAB>
__device__ __forceinline__ int sink_pass1(float (&P)[NR][WAYS], float ctot,
                                          int lane, int cls) {
  float u[NR];
  #pragma unroll
  for (int s = 0; s < NR; s++) u[s] = 0.f;
  int b = 0;
  for (;;) {
    float rs[NR];
    float d = 0.f;
    #pragma unroll
    for (int s = 0; s < NR; s++) {
      rs[s] = P[s][0] + P[s][1] + P[s][2] + P[s][3] + P[s][4];
      if (lane + 32 * s < NROWS) d = fmaxf(d, fabsf(u[s] - rs[s]));
    }
    float delta = wmax_x(d);
    float t[NR][WAYS];
    float cp[WAYS] = {0.f, 0.f, 0.f, 0.f, 0.f};
    #pragma unroll
    for (int s = 0; s < NR; s++) {
      float inv = (lane + 32 * s < NROWS) ? (1.0f / rs[s]) : 0.f;
      #pragma unroll
      for (int k = 0; k < WAYS; k++) { t[s][k] = P[s][k] * inv; cp[k] += t[s][k]; }
    }
    float f[WAYS];
    #pragma unroll
    for (int k = 0; k < WAYS; k++) f[k] = ctot / wsum_x(cp[k]);
    #pragma unroll
    for (int s = 0; s < NR; s++)
      #pragma unroll
      for (int k = 0; k < WAYS; k++) t[s][k] *= f[k];
    if (LAB && lane < NSUP) {
      #pragma unroll
      for (int k = 0; k < WAYS; k++) t[0][k] = (k == cls) ? 1.f : 0.f;
    }
    if (!(delta > EPSV && b < MAXIT)) break;
    #pragma unroll
    for (int s = 0; s < NR; s++) {
      u[s] = rs[s];
      #pragma unroll
      for (int k = 0; k < WAYS; k++) P[s][k] = t[s][k];
    }
    b++;
  }
  return b;
}

// ---- single-warp register sinkhorn: replay exactly `iters` bodies ----------
template<int NR, int NROWS, bool LAB>
__device__ __forceinline__ void sink_replay(float (&P)[NR][WAYS], float ctot,
                                            int lane, int cls, int iters) {
  for (int it = 0; it < iters; it++) {
    float cp[WAYS] = {0.f, 0.f, 0.f, 0.f, 0.f};
    #pragma unroll
    for (int s = 0; s < NR; s++) {
      float rs = P[s][0] + P[s][1] + P[s][2] + P[s][3] + P[s][4];
      float inv = (lane + 32 * s < NROWS) ? (1.0f / rs) : 0.f;
      #pragma unroll
      for (int k = 0; k < WAYS; k++) { P[s][k] *= inv; cp[k] += P[s][k]; }
    }
    float f[WAYS];
    #pragma unroll
    for (int k = 0; k < WAYS; k++) f[k] = ctot / wsum_x(cp[k]);
    #pragma unroll
    for (int s = 0; s < NR; s++)
      #pragma unroll
      for (int k = 0; k < WAYS; k++) P[s][k] *= f[k];
    if (LAB && lane < NSUP) {
      #pragma unroll
      for (int k = 0; k < WAYS; k++) P[0][k] = (k == cls) ? 1.f : 0.f;
    }
  }
}

// ---------------- KA: epoch-0 proto, Pq0, sinkhorn1 pass-1 ------------------
__global__ __launch_bounds__(160) void ka_kernel(const float* __restrict__ xs,
                                                 const float* __restrict__ xq) {
  __shared__ float ps[WAYS][DIM];
  __shared__ float pn[WAYS];
  __shared__ float Psh[NQ][WAYS];
  int run = blockIdx.x;
  int tid = threadIdx.x, w = tid >> 5, lane = tid & 31;
  const float* xsr = xs + (size_t)run * NSUP * DIM;
  const float* xqr = xq + (size_t)run * NQ * DIM;

  for (int idx = tid; idx < WAYS * DIM; idx += 160) {
    int k = idx / DIM, d = idx % DIM;
    float s = 0.f;
    #pragma unroll
    for (int sh = 0; sh < SHOT; sh++) s += xsr[(k * SHOT + sh) * DIM + d];
    float v = s / 5.0f;
    ps[k][d] = v;
    g_proto[run][k][d] = v;
  }
  __syncthreads();

  { // proto norms (warp w does class w)
    float a = 0.f;
    for (int d = lane; d < DIM; d += 32) { float v = ps[w][d]; a += v * v; }
    a = wred(a);
    if (lane == 0) pn[w] = a;
  }
  __syncthreads();

  // Pq = exp(-LAM * d2(query, proto))
  for (int q = w; q < NQ; q += 5) {
    float a0=0,a1=0,a2=0,a3=0,a4=0,an=0;
    const float* xr = xqr + q * DIM;
    #pragma unroll 4
    for (int d = lane; d < DIM; d += 32) {
      float x = xr[d];
      an += x*x;
      a0 += x*ps[0][d]; a1 += x*ps[1][d]; a2 += x*ps[2][d];
      a3 += x*ps[3][d]; a4 += x*ps[4][d];
    }
    an = wred(an); a0 = wred(a0); a1 = wred(a1); a2 = wred(a2); a3 = wred(a3); a4 = wred(a4);
    if (lane == 0) {
      float acc[5] = {a0,a1,a2,a3,a4};
      #pragma unroll
      for (int k = 0; k < WAYS; k++) {
        float d2 = fmaxf(an + pn[k] - 2.0f * acc[k], 0.0f);
        Psh[q][k] = expf(-LAM * d2);
      }
    }
  }
  __syncthreads();

  if (tid < 32) {
    float P[3][WAYS];
    #pragma unroll
    for (int s = 0; s < 3; s++) {
      int row = lane + 32 * s;
      #pragma unroll
      for (int k = 0; k < WAYS; k++) P[s][k] = (row < NQ) ? Psh[row][k] : 0.f;
    }
    int b = sink_pass1<3, NQ, false>(P, 15.0f, lane, 0);
    #pragma unroll
    for (int s = 0; s < 3; s++) {
      int row = lane + 32 * s;
      if (row < NQ)
        #pragma unroll
        for (int k = 0; k < WAYS; k++) g_P1[run][row][k] = P[s][k];
    }
    if (lane == 0) g_b1A[run] = b;
  }
}

// ---- KB (fused): replay sinkhorn1(e), entropy, blend; then either
//      Pq+pass-1 for epoch e+1 (e<2) or the epoch-2 tail (Fp/Zext). ---------
__global__ __launch_bounds__(160) void kb_kernel(const float* __restrict__ xs,
                                                 const float* __restrict__ xq,
                                                 const int* __restrict__ ys,
                                                 int epoch) {
  __shared__ float Psh[NQ][WAYS];
  __shared__ float Z[NF][WAYS];
  __shared__ float ent[NF];
  __shared__ float cs[WAYS];
  __shared__ float psh[WAYS][DIM];
  __shared__ float pn2[WAYS];
  __shared__ float dp[WAYS][WAYS];
  __shared__ float score[WAYS], maskv[WAYS];
  __shared__ float omega_s;
  int run = blockIdx.x, tid = threadIdx.x;
  int w = tid >> 5, lane = tid & 31;
  const int* ysr = ys + run * NSUP;
  const float* xsr = xs + (size_t)run * NSUP * DIM;
  const float* xqr = xq + (size_t)run * NQ * DIM;

  const int* rbuf = (epoch == 1) ? g_b1B : g_b1A;   // pass-1 counts for epoch e
  int* wbuf = (epoch == 0) ? g_b1B : g_b1A;          // counts for epoch e+1

  if (tid < 32) {  // warp 0: replay to global B, registers only
    float P[3][WAYS];
    #pragma unroll
    for (int s = 0; s < 3; s++) {
      int row = lane + 32 * s;
      #pragma unroll
      for (int k = 0; k < WAYS; k++) P[s][k] = (row < NQ) ? g_P1[run][row][k] : 0.f;
    }
    int m = 0;
    for (int i = lane; i < RUNS; i += 32) m = max(m, rbuf[i]);
    m = __reduce_max_sync(0xffffffffu, m);
    int extra = m - rbuf[run];
    sink_replay<3, NQ, false>(P, 15.0f, lane, 0, extra);
    #pragma unroll
    for (int s = 0; s < 3; s++) {
      int row = lane + 32 * s;
      if (row < NQ)
        #pragma unroll
        for (int k = 0; k < WAYS; k++) Psh[row][k] = P[s][k];
    }
  } else {
    // warps 1-4: prefetch the feature block to L2 while warp 0 replays
    int t4 = (w - 1) * 32 + lane;   // 0..127
    for (int off = t4 * 32; off < NSUP * DIM; off += 128 * 32)
      asm volatile("prefetch.global.L2 [%0];" :: "l"(xsr + off));
    for (int off = t4 * 32; off < NQ * DIM; off += 128 * 32)
      asm volatile("prefetch.global.L2 [%0];" :: "l"(xqr + off));
  }
  __syncthreads();

  // Z = [onehot(ys); Pq]
  for (int idx = tid; idx < NF * WAYS; idx += 160) {
    int i = idx / WAYS, k = idx % WAYS;
    float v = (i < NSUP) ? ((ysr[i] == k) ? 1.0f : 0.0f) : Psh[i - NSUP][k];
    Z[i][k] = v;
  }
  __syncthreads();

  // entropy per row
  if (tid < NF) {
    float p[WAYS], s = 0.f;
    #pragma unroll
    for (int k = 0; k < WAYS; k++) { p[k] = Z[tid][k] + 1e-12f; s += p[k]; }
    float H = 0.f;
    #pragma unroll
    for (int k = 0; k < WAYS; k++) { float q = p[k] / s; H -= q * logf(q); }
    ent[tid] = H / logf(5.0f);
  }
  __syncthreads();

  // Z *= (1 - ent)
  for (int idx = tid; idx < NF * WAYS; idx += 160) {
    int i = idx / WAYS;
    ((float*)Z)[idx] *= (1.0f - ent[i]);
  }
  __syncthreads();
  { // column sums via warp reductions (warp w -> class w)
    float part = 0.f;
    for (int i = lane; i < NF; i += 32) part += Z[i][w];
    part = wred(part);
    if (lane == 0) cs[w] = part;
  }
  __syncthreads();

  // new_proto + blend: row-outer loop, 4 independent column streams (MLP)
  {
    float a[4][WAYS];
    #pragma unroll
    for (int d = 0; d < 4; d++)
      #pragma unroll
      for (int k = 0; k < WAYS; k++) a[d][k] = 0.f;
    #pragma unroll 2
    for (int i = 0; i < NF; i++) {
      const float* fr = (i < NSUP) ? (xsr + i * DIM)
                                   : (xqr + (size_t)(i - NSUP) * DIM);
      float f0 = fr[tid], f1 = fr[tid + 160], f2 = fr[tid + 320], f3 = fr[tid + 480];
      #pragma unroll
      for (int k = 0; k < WAYS; k++) {
        float z = Z[i][k];
        a[0][k] += z * f0; a[1][k] += z * f1; a[2][k] += z * f2; a[3][k] += z * f3;
      }
    }
    #pragma unroll
    for (int d = 0; d < 4; d++) {
      int dcol = tid + d * 160;
      #pragma unroll
      for (int k = 0; k < WAYS; k++) {
        float np = a[d][k] / cs[k];
        float pr = 0.4f * g_proto[run][k][dcol] + 0.6f * np;
        g_proto[run][k][dcol] = pr;
        psh[k][dcol] = pr;
      }
    }
  }
  __syncthreads();

  { // new proto norms (warp w -> class w); needed by both branches
    float a = 0.f;
    for (int d = lane; d < DIM; d += 32) { float v = psh[w][d]; a += v * v; }
    a = wred(a);
    if (lane == 0) pn2[w] = a;
  }
  __syncthreads();

  if (epoch < 2) {
    // ---- fused "ka" for epoch e+1: Pq from psh, then pass-1 ----
    for (int q = w; q < NQ; q += 5) {
      float a0=0,a1=0,a2=0,a3=0,a4=0,an=0;
      const float* xr = xqr + q * DIM;
      #pragma unroll 4
      for (int d = lane; d < DIM; d += 32) {
        float x = xr[d];
        an += x*x;
        a0 += x*psh[0][d]; a1 += x*psh[1][d]; a2 += x*psh[2][d];
        a3 += x*psh[3][d]; a4 += x*psh[4][d];
      }
      an = wred(an); a0 = wred(a0); a1 = wred(a1); a2 = wred(a2); a3 = wred(a3); a4 = wred(a4);
      if (lane == 0) {
        float acc[5] = {a0,a1,a2,a3,a4};
        #pragma unroll
        for (int k = 0; k < WAYS; k++) {
          float d2 = fmaxf(an + pn2[k] - 2.0f * acc[k], 0.0f);
          Psh[q][k] = expf(-LAM * d2);
        }
      }
    }
    __syncthreads();
    if (tid < 32) {
      float P[3][WAYS];
      #pragma unroll
      for (int s = 0; s < 3; s++) {
        int row = lane + 32 * s;
        #pragma unroll
        for (int k = 0; k < WAYS; k++) P[s][k] = (row < NQ) ? Psh[row][k] : 0.f;
      }
      int b = sink_pass1<3, NQ, false>(P, 15.0f, lane, 0);
      #pragma unroll
      for (int s = 0; s < 3; s++) {
        int row = lane + 32 * s;
        if (row < NQ)
          #pragma unroll
          for (int k = 0; k < WAYS; k++) g_P1[run][row][k] = P[s][k];
      }
      if (lane == 0) wbuf[run] = b;
    }
  } else {
    // ---- epoch-2 tail: proto distance graph, mask, Fp/Zext ----
    for (int p = w; p < WAYS * WAYS; p += 5) {
      int ia = p / WAYS, ib = p % WAYS;
      float acc = 0.f;
      for (int d = lane; d < DIM; d += 32) acc += psh[ia][d] * psh[ib][d];
      acc = wred(acc);
      if (lane == 0) {
        float d2 = fmaxf(pn2[ia] + pn2[ib] - 2.0f * acc, 0.0f);
        dp[ia][ib] = expf(-LAM * d2);
      }
    }
    __syncthreads();
    if (tid < WAYS) {
      float p[WAYS], s = 0.f;
      #pragma unroll
      for (int k = 0; k < WAYS; k++) { p[k] = dp[tid][k] + 1e-12f; s += p[k]; }
      float H = 0.f;
      #pragma unroll
      for (int k = 0; k < WAYS; k++) { float q = p[k] / s; H -= q * logf(q); }
      score[tid] = H / logf(5.0f);
    }
    if (w == 0) { // omega = mean(ent)
      float part = 0.f;
      for (int i = lane; i < NF; i += 32) part += ent[i];
      part = wred(part);
      if (lane == 0) omega_s = part / 100.0f;
    }
    __syncthreads();
    if (tid < WAYS) maskv[tid] = (score[tid] < omega_s) ? 1.0f : 0.0f;
    __syncthreads();
    for (int idx = tid; idx < WAYS * DIM; idx += 160) {
      int k = idx / DIM, d = idx % DIM;
      g_Fp[run][k][d] = psh[k][d] * maskv[k];
    }
    for (int idx = tid; idx < NF * WAYS; idx += 160) {
      int i = idx / WAYS, k = idx % WAYS;
      g_Zext[run][i][k] = Z[i][k];
    }
    if (tid < WAYS * WAYS) {
      int ia = tid / WAYS, k = tid % WAYS;
      g_Zext[run][NF + ia][k] = dp[ia][k] * maskv[ia];
    }
  }
}

// ---------------- KC: symmetric Gram + graph + register Cholesky + solves --
#define FROWS 112
#define KCHUNK 32
#define FPAD 33
#define KC_SMEM (NTOT * NTOT * 4)   // 44,100B (>= FROWS*FPAD*4 = 14,784B)

__global__ __launch_bounds__(256, 2) void kc_kernel(const float* __restrict__ xs,
                                                    const float* __restrict__ xq,
                                                    const int* __restrict__ ys) {
  extern __shared__ float sm[];
  float* Fsh = sm;                  // phase 1 (Gram)
  float* As  = sm;                  // phase 2 (S matrix; Fsh dead)
  float* Lsh = sm;                  // phase 3 (L; As dead)
  __shared__ float n2[FROWS];
  __shared__ float rsum[FROWS];
  __shared__ float Dm[FROWS];
  __shared__ float colbuf[2][FROWS];
  __shared__ float sh_piv;
  __shared__ float yv[NTOT][WAYS];

  int run = blockIdx.x, tid = threadIdx.x;
  int ti = tid >> 4, tj = tid & 15;      // grid mapping (Cholesky phase)
  int w = tid >> 5, lane = tid & 31;
  const float* xsr = xs + (size_t)run * NSUP * DIM;
  const float* xqr = xq + (size_t)run * NQ * DIM;
  const int* ysr = ys + run * NSUP;

  // triangular tile mapping for the Gram: threads 0..135 own tiles ti>=tj,
  // packed so warps 5..7 are fully idle (predicated lanes still cost issue).
  bool act = tid < 136;
  int tix = 0, tjx = 0;
  if (act) {
    tix = (int)((sqrtf(8.0f * (float)tid + 1.0f) - 1.0f) * 0.5f);
    while ((tix + 1) * (tix + 2) / 2 <= tid) tix++;
    while (tix * (tix + 1) / 2 > tid) tix--;
    tjx = tid - tix * (tix + 1) / 2;
  }

  float acc[7][7];
  #pragma unroll
  for (int r = 0; r < 7; r++)
    #pragma unroll
    for (int c = 0; c < 7; c++) acc[r][c] = 0.f;

  // ---- Gram (lower-triangle tiles only) ----
  for (int c0 = 0; c0 < DIM; c0 += KCHUNK) {
    __syncthreads();
    for (int e = tid; e < FROWS * KCHUNK; e += 256) {
      int r = e >> 5, dd = e & 31;
      float v = 0.f;
      if (r < NSUP)       v = xsr[r * DIM + c0 + dd];
      else if (r < NF)    v = xqr[(r - NSUP) * DIM + c0 + dd];
      else if (r < NTOT)  v = g_Fp[run][r - NF][c0 + dd];
      Fsh[r * FPAD + dd] = v;
    }
    __syncthreads();
    if (act) {
      #pragma unroll 4
      for (int dd = 0; dd < KCHUNK; dd++) {
        float a[7], bv[7];
        #pragma unroll
        for (int r = 0; r < 7; r++) a[r] = Fsh[(tix * 7 + r) * FPAD + dd];
        #pragma unroll
        for (int c = 0; c < 7; c++) bv[c] = Fsh[(tjx * 7 + c) * FPAD + dd];
        #pragma unroll
        for (int r = 0; r < 7; r++)
          #pragma unroll
          for (int c = 0; c < 7; c++) acc[r][c] += a[r] * bv[c];
      }
    }
  }
  __syncthreads();

  // ---- materialize S (both halves) in shared ----
  if (act) {
    #pragma unroll
    for (int r = 0; r < 7; r++) {
      int gi = tix * 7 + r;
      #pragma unroll
      for (int c = 0; c < 7; c++) {
        int gj = tjx * 7 + c;
        if (gi < NTOT && gj < NTOT) As[gi * NTOT + gj] = acc[r][c];
      }
    }
    if (tix > tjx) {
      #pragma unroll
      for (int r = 0; r < 7; r++) {
        int gi = tix * 7 + r;
        #pragma unroll
        for (int c = 0; c < 7; c++) {
          int gj = tjx * 7 + c;
          if (gi < NTOT && gj < NTOT) As[gj * NTOT + gi] = acc[r][c];
        }
      }
    }
  }
  __syncthreads();

  // ---- diag norms ----
  if (tid < FROWS) {
    n2[tid] = (tid < NTOT) ? As[tid * NTOT + tid] : 0.f;
    rsum[tid] = 0.f;
  }
  __syncthreads();

  // ---- every thread takes its GRID tile: W = exp(-LAM*d2), rowsums --------
  #pragma unroll
  for (int r = 0; r < 7; r++) {
    int gi = ti * 7 + r;
    #pragma unroll
    for (int c = 0; c < 7; c++) {
      int gj = tj * 7 + c;
      float wv = 0.f;
      if (gi < NTOT && gj < NTOT && gi != gj) {
        float d2 = fmaxf(n2[gi] + n2[gj] - 2.0f * As[gi * NTOT + gj], 0.0f);
        wv = expf(-LAM * d2);
      }
      acc[r][c] = wv;
    }
  }
  #pragma unroll
  for (int r = 0; r < 7; r++) {
    int gi = ti * 7 + r;
    float p = 0.f;
    #pragma unroll
    for (int c = 0; c < 7; c++) p += acc[r][c];
    if (gi < NTOT) atomicAdd(&rsum[gi], p);
  }
  __syncthreads();
  if (tid < FROWS) Dm[tid] = (tid < NTOT) ? (1.0f / sqrtf(rsum[tid])) : 0.f;
  __syncthreads();

  // ---- A = I - ALPHA * Dm_i W Dm_j (in registers) ----
  #pragma unroll
  for (int r = 0; r < 7; r++) {
    int gi = ti * 7 + r;
    float di = Dm[gi];
    #pragma unroll
    for (int c = 0; c < 7; c++) {
      int gj = tj * 7 + c;
      acc[r][c] = ((gi == gj) ? 1.0f : 0.0f) - ALPHA_ * di * acc[r][c] * Dm[gj];
    }
  }
  __syncthreads();

  // ---- register-resident Cholesky, rank-1 updates via shared column bcast --
  for (int jt = 0; jt < 15; jt++) {
    #pragma unroll
    for (int jc = 0; jc < 7; jc++) {
      int j = jt * 7 + jc;
      int buf = j & 1;
      if (tid < FROWS) colbuf[buf][tid] = 0.f;
      if (ti == jt && tj == jt) {
        float pv = sqrtf(acc[jc][jc]);
        acc[jc][jc] = pv;
        sh_piv = pv;
      }
      __syncthreads();
      if (tj == jt) {
        float ip = 1.0f / sh_piv;
        #pragma unroll
        for (int r = 0; r < 7; r++) {
          int gi = ti * 7 + r;
          if (gi > j) { acc[r][jc] *= ip; colbuf[buf][gi] = acc[r][jc]; }
        }
      }
      __syncthreads();
      float rv[7], cv[7];
      #pragma unroll
      for (int r = 0; r < 7; r++) rv[r] = colbuf[buf][ti * 7 + r];
      #pragma unroll
      for (int c = 0; c < 7; c++) cv[c] = colbuf[buf][tj * 7 + c];
      #pragma unroll
      for (int r = 0; r < 7; r++)
        #pragma unroll
        for (int c = 0; c < 7; c++) acc[r][c] -= rv[r] * cv[c];
    }
  }
  __syncthreads();   // As region dead; reuse as Lsh

  // ---- dump L (lower + diag) to shared ----
  #pragma unroll
  for (int r = 0; r < 7; r++) {
    int gi = ti * 7 + r;
    #pragma unroll
    for (int c = 0; c < 7; c++) {
      int gj = tj * 7 + c;
      if (gi < NTOT && gj < NTOT && gj <= gi) Lsh[gi * NTOT + gj] = acc[r][c];
    }
  }
  for (int idx = tid; idx < NTOT * WAYS; idx += 256)
    ((float*)yv)[idx] = ((const float*)g_Zext[run])[idx];
  __syncthreads();

  // ---- triangular solves: warp w handles RHS column w ----
  if (w < WAYS) {
    for (int i = 0; i < NTOT; i++) {
      float part = 0.f;
      for (int jj = lane; jj < i; jj += 32) part += Lsh[i * NTOT + jj] * yv[jj][w];
      part = wred(part);
      if (lane == 0) yv[i][w] = (yv[i][w] - part) / Lsh[i * NTOT + i];
      __syncwarp();
    }
    for (int i = NTOT - 1; i >= 0; i--) {
      float part = 0.f;
      for (int jj = i + 1 + lane; jj < NTOT; jj += 32) part += Lsh[jj * NTOT + i] * yv[jj][w];
      part = wred(part);
      if (lane == 0) yv[i][w] = (yv[i][w] - part) / Lsh[i * NTOT + i];
      __syncwarp();
    }
  }
  __syncthreads();

  // ---- sinkhorn2 pass-1: warp 0, registers ----
  if (tid < 32) {
    float P[4][WAYS];
    #pragma unroll
    for (int s = 0; s < 4; s++) {
      int row = lane + 32 * s;
      #pragma unroll
      for (int k = 0; k < WAYS; k++) P[s][k] = (row < NTOT) ? yv[row][k] : 0.f;
    }
    int cls = (lane < NSUP) ? ysr[lane] : 0;
    int b = sink_pass1<4, NTOT, true>(P, 21.0f, lane, cls);
    #pragma unroll
    for (int s = 0; s < 4; s++) {
      int row = lane + 32 * s;
      if (row < NTOT)
        #pragma unroll
        for (int k = 0; k < WAYS; k++) g_Z0[run][row][k] = P[s][k];
    }
    if (lane == 0) g_b2run[run] = b;
  }
}

// ---------------- KD: 1 warp per run: replay sinkhorn2, argmax, accuracy ----
__global__ __launch_bounds__(128) void kd_kernel(const int* __restrict__ ys,
                                                 const int* __restrict__ yq,
                                                 float* __restrict__ out) {
  int tid = threadIdx.x, w = tid >> 5, lane = tid & 31;
  int run = blockIdx.x * 4 + w;
  const int* ysr = ys + run * NSUP;
  float P[4][WAYS];
  #pragma unroll
  for (int s = 0; s < 4; s++) {
    int row = lane + 32 * s;
    #pragma unroll
    for (int k = 0; k < WAYS; k++) P[s][k] = (row < NTOT) ? g_Z0[run][row][k] : 0.f;
  }
  int cls = (lane < NSUP) ? ysr[lane] : 0;
  int m = 0;
  for (int i = lane; i < RUNS; i += 32) m = max(m, g_b2run[i]);
  m = __reduce_max_sync(0xffffffffu, m);
  int extra = m - g_b2run[run];
  sink_replay<4, NTOT, true>(P, 21.0f, lane, cls, extra);

  int cnt = 0;
  #pragma unroll
  for (int s = 0; s < 4; s++) {
    int row = lane + 32 * s;
    if (row >= NSUP && row < NF) {
      float best = P[s][0]; int bi = 0;
      #pragma unroll
      for (int k = 1; k < WAYS; k++)
        if (P[s][k] > best) { best = P[s][k]; bi = k; }
      if (bi == yq[run * NQ + (row - NSUP)]) cnt++;
    }
  }
  #pragma unroll
  for (int o = 16; o; o >>= 1) cnt += __shfl_xor_sync(0xffffffffu, cnt, o);
  if (lane == 0) out[run] = (float)cnt / 75.0f;
}

// ---------------------------------------------------------------------------
extern "C" void kernel_launch(void* const* d_in, const int* in_sizes, int n_in,
                              void* d_out, int out_size) {
  const float* xs = (const float*)d_in[0];
  const float* xq = (const float*)d_in[1];
  const int*   ys = (const int*)d_in[2];
  const int*   yq = (const int*)d_in[3];
  float* out = (float*)d_out;

  cudaFuncSetAttribute(kc_kernel, cudaFuncAttributeMaxDynamicSharedMemorySize,
                       KC_SMEM);

  ka_kernel<<<RUNS, 160>>>(xs, xq);
  for (int e = 0; e < 3; e++)
    kb_kernel<<<RUNS, 160>>>(xs, xq, ys, e);
  kc_kernel<<<RUNS, 256, KC_SMEM>>>(xs, xq, ys);
  kd_kernel<<<RUNS / 4, 128>>>(ys, yq, out);
}

// round 9
// speedup vs baseline: 1.5743x; 1.0016x over previous
#include <cuda_runtime.h>
#include <math.h>
#include <stdint.h>

#define RUNS 512
#define WAYS 5
#define SHOT 5
#define NSUP 25
#define NQ   75
#define NF   100
#define NTOT 105
#define DIM  640
#define LAM  10.0f
#define ALPHA_ 0.7f
#define EPSV 1e-3f
#define MAXIT 1000

// ---------------- device scratch (static: no allocations allowed) ----------
__device__ float g_proto[RUNS][WAYS][DIM];
__device__ float g_Fp[RUNS][WAYS][DIM];     // masked proto rows (epoch 2)
__device__ float g_P1[RUNS][NQ][WAYS];      // sinkhorn1 state after pass-1
__device__ int   g_b1A[RUNS];               // per-run body counts (double buf)
__device__ int   g_b1B[RUNS];
__device__ float g_Zext[RUNS][NTOT][WAYS];  // extended Z (epoch 2, pre-solve)
__device__ float g_Z0[RUNS][NTOT][WAYS];    // solved Z / sinkhorn2 state
__device__ int   g_b2run[RUNS];

__device__ __forceinline__ float wred(float v) {
  #pragma unroll
  for (int o = 16; o; o >>= 1) v += __shfl_down_sync(0xffffffffu, v, o);
  return v;
}
__device__ __forceinline__ float wsum_x(float v) {
  #pragma unroll
  for (int o = 16; o; o >>= 1) v += __shfl_xor_sync(0xffffffffu, v, o);
  return v;
}
__device__ __forceinline__ float wmax_x(float v) {
  #pragma unroll
  for (int o = 16; o; o >>= 1) v = fmaxf(v, __shfl_xor_sync(0xffffffffu, v, o));
  return v;
}
__device__ __forceinline__ float fdiv(float a, float b) { return __fdividef(a, b); }

// ---- single-warp register sinkhorn: pass-1 (count bodies to own converge) --
template<int NR, int NROWS, bool LAB>
__device__ __forceinline__ int sink_pass1(float (&P)[NR][WAYS], float ctot,
                                          int lane, int cls) {
  float u[NR];
  #pragma unroll
  for (int s = 0; s < NR; s++) u[s] = 0.f;
  int b = 0;
  for (;;) {
    float rs[NR];
    float d = 0.f;
    #pragma unroll
    for (int s = 0; s < NR; s++) {
      rs[s] = P[s][0] + P[s][1] + P[s][2] + P[s][3] + P[s][4];
      if (lane + 32 * s < NROWS) d = fmaxf(d, fabsf(u[s] - rs[s]));
    }
    float delta = wmax_x(d);
    float t[NR][WAYS];
    float cp[WAYS] = {0.f, 0.f, 0.f, 0.f, 0.f};
    #pragma unroll
    for (int s = 0; s < NR; s++) {
      float inv = (lane + 32 * s < NROWS) ? fdiv(1.0f, rs[s]) : 0.f;
      #pragma unroll
      for (int k = 0; k < WAYS; k++) { t[s][k] = P[s][k] * inv; cp[k] += t[s][k]; }
    }
    float f[WAYS];
    #pragma unroll
    for (int k = 0; k < WAYS; k++) f[k] = fdiv(ctot, wsum_x(cp[k]));
    #pragma unroll
    for (int s = 0; s < NR; s++)
      #pragma unroll
      for (int k = 0; k < WAYS; k++) t[s][k] *= f[k];
    if (LAB && lane < NSUP) {
      #pragma unroll
      for (int k = 0; k < WAYS; k++) t[0][k] = (k == cls) ? 1.f : 0.f;
    }
    if (!(delta > EPSV && b < MAXIT)) break;
    #pragma unroll
    for (int s = 0; s < NR; s++) {
      u[s] = rs[s];
      #pragma unroll
      for (int k = 0; k < WAYS; k++) P[s][k] = t[s][k];
    }
    b++;
  }
  return b;
}

// ---- single-warp register sinkhorn: replay exactly `iters` bodies ----------
template<int NR, int NROWS, bool LAB>
__device__ __forceinline__ void sink_replay(float (&P)[NR][WAYS], float ctot,
                                            int lane, int cls, int iters) {
  for (int it = 0; it < iters; it++) {
    float cp[WAYS] = {0.f, 0.f, 0.f, 0.f, 0.f};
    #pragma unroll
    for (int s = 0; s < NR; s++) {
      float rs = P[s][0] + P[s][1] + P[s][2] + P[s][3] + P[s][4];
      float inv = (lane + 32 * s < NROWS) ? fdiv(1.0f, rs) : 0.f;
      #pragma unroll
      for (int k = 0; k < WAYS; k++) { P[s][k] *= inv; cp[k] += P[s][k]; }
    }
    float f[WAYS];
    #pragma unroll
    for (int k = 0; k < WAYS; k++) f[k] = fdiv(ctot, wsum_x(cp[k]));
    #pragma unroll
    for (int s = 0; s < NR; s++)
      #pragma unroll
      for (int k = 0; k < WAYS; k++) P[s][k] *= f[k];
    if (LAB && lane < NSUP) {
      #pragma unroll
      for (int k = 0; k < WAYS; k++) P[0][k] = (k == cls) ? 1.f : 0.f;
    }
  }
}

// ---------------- KA: epoch-0 proto, Pq0, sinkhorn1 pass-1 ------------------
__global__ __launch_bounds__(160) void ka_kernel(const float* __restrict__ xs,
                                                 const float* __restrict__ xq) {
  __shared__ float ps[WAYS][DIM];
  __shared__ float pn[WAYS];
  __shared__ float Psh[NQ][WAYS];
  int run = blockIdx.x;
  int tid = threadIdx.x, w = tid >> 5, lane = tid & 31;
  const float* xsr = xs + (size_t)run * NSUP * DIM;
  const float* xqr = xq + (size_t)run * NQ * DIM;

  for (int idx = tid; idx < WAYS * DIM; idx += 160) {
    int k = idx / DIM, d = idx % DIM;
    float s = 0.f;
    #pragma unroll
    for (int sh = 0; sh < SHOT; sh++) s += xsr[(k * SHOT + sh) * DIM + d];
    float v = s / 5.0f;
    ps[k][d] = v;
    g_proto[run][k][d] = v;
  }
  __syncthreads();

  { // proto norms (warp w does class w)
    float a = 0.f;
    for (int d = lane; d < DIM; d += 32) { float v = ps[w][d]; a += v * v; }
    a = wred(a);
    if (lane == 0) pn[w] = a;
  }
  __syncthreads();

  // Pq = exp(-LAM * d2(query, proto))
  for (int q = w; q < NQ; q += 5) {
    float a0=0,a1=0,a2=0,a3=0,a4=0,an=0;
    const float* xr = xqr + q * DIM;
    #pragma unroll 4
    for (int d = lane; d < DIM; d += 32) {
      float x = xr[d];
      an += x*x;
      a0 += x*ps[0][d]; a1 += x*ps[1][d]; a2 += x*ps[2][d];
      a3 += x*ps[3][d]; a4 += x*ps[4][d];
    }
    an = wred(an); a0 = wred(a0); a1 = wred(a1); a2 = wred(a2); a3 = wred(a3); a4 = wred(a4);
    if (lane == 0) {
      float acc[5] = {a0,a1,a2,a3,a4};
      #pragma unroll
      for (int k = 0; k < WAYS; k++) {
        float d2 = fmaxf(an + pn[k] - 2.0f * acc[k], 0.0f);
        Psh[q][k] = expf(-LAM * d2);
      }
    }
  }
  __syncthreads();

  if (tid < 32) {
    float P[3][WAYS];
    #pragma unroll
    for (int s = 0; s < 3; s++) {
      int row = lane + 32 * s;
      #pragma unroll
      for (int k = 0; k < WAYS; k++) P[s][k] = (row < NQ) ? Psh[row][k] : 0.f;
    }
    int b = sink_pass1<3, NQ, false>(P, 15.0f, lane, 0);
    #pragma unroll
    for (int s = 0; s < 3; s++) {
      int row = lane + 32 * s;
      if (row < NQ)
        #pragma unroll
        for (int k = 0; k < WAYS; k++) g_P1[run][row][k] = P[s][k];
    }
    if (lane == 0) g_b1A[run] = b;
  }
}

// ---- KB (fused): replay sinkhorn1(e), entropy, blend; then either
//      Pq+pass-1 for epoch e+1 (e<2) or the epoch-2 tail (Fp/Zext). ---------
__global__ __launch_bounds__(160) void kb_kernel(const float* __restrict__ xs,
                                                 const float* __restrict__ xq,
                                                 const int* __restrict__ ys,
                                                 int epoch) {
  __shared__ float Psh[NQ][WAYS];
  __shared__ float Z[NF][WAYS];
  __shared__ float ent[NF];
  __shared__ float cs[WAYS];
  __shared__ float psh[WAYS][DIM];
  __shared__ float pn2[WAYS];
  __shared__ float dp[WAYS][WAYS];
  __shared__ float score[WAYS], maskv[WAYS];
  __shared__ float omega_s;
  int run = blockIdx.x, tid = threadIdx.x;
  int w = tid >> 5, lane = tid & 31;
  const int* ysr = ys + run * NSUP;
  const float* xsr = xs + (size_t)run * NSUP * DIM;
  const float* xqr = xq + (size_t)run * NQ * DIM;

  const int* rbuf = (epoch == 1) ? g_b1B : g_b1A;   // pass-1 counts for epoch e
  int* wbuf = (epoch == 0) ? g_b1B : g_b1A;          // counts for epoch e+1

  if (tid < 32) {  // warp 0: replay to global B, registers only
    float P[3][WAYS];
    #pragma unroll
    for (int s = 0; s < 3; s++) {
      int row = lane + 32 * s;
      #pragma unroll
      for (int k = 0; k < WAYS; k++) P[s][k] = (row < NQ) ? g_P1[run][row][k] : 0.f;
    }
    int m = 0;
    for (int i = lane; i < RUNS; i += 32) m = max(m, rbuf[i]);
    m = __reduce_max_sync(0xffffffffu, m);
    int extra = m - rbuf[run];
    sink_replay<3, NQ, false>(P, 15.0f, lane, 0, extra);
    #pragma unroll
    for (int s = 0; s < 3; s++) {
      int row = lane + 32 * s;
      if (row < NQ)
        #pragma unroll
        for (int k = 0; k < WAYS; k++) Psh[row][k] = P[s][k];
    }
  } else {
    // warps 1-4: prefetch the feature block to L2 while warp 0 replays
    int t4 = (w - 1) * 32 + lane;   // 0..127
    for (int off = t4 * 32; off < NSUP * DIM; off += 128 * 32)
      asm volatile("prefetch.global.L2 [%0];" :: "l"(xsr + off));
    for (int off = t4 * 32; off < NQ * DIM; off += 128 * 32)
      asm volatile("prefetch.global.L2 [%0];" :: "l"(xqr + off));
  }
  __syncthreads();

  // Z = [onehot(ys); Pq]
  for (int idx = tid; idx < NF * WAYS; idx += 160) {
    int i = idx / WAYS, k = idx % WAYS;
    float v = (i < NSUP) ? ((ysr[i] == k) ? 1.0f : 0.0f) : Psh[i - NSUP][k];
    Z[i][k] = v;
  }
  __syncthreads();

  // entropy per row
  if (tid < NF) {
    float p[WAYS], s = 0.f;
    #pragma unroll
    for (int k = 0; k < WAYS; k++) { p[k] = Z[tid][k] + 1e-12f; s += p[k]; }
    float H = 0.f;
    #pragma unroll
    for (int k = 0; k < WAYS; k++) { float q = p[k] / s; H -= q * logf(q); }
    ent[tid] = H / logf(5.0f);
  }
  __syncthreads();

  // Z *= (1 - ent)
  for (int idx = tid; idx < NF * WAYS; idx += 160) {
    int i = idx / WAYS;
    ((float*)Z)[idx] *= (1.0f - ent[i]);
  }
  __syncthreads();
  { // column sums via warp reductions (warp w -> class w)
    float part = 0.f;
    for (int i = lane; i < NF; i += 32) part += Z[i][w];
    part = wred(part);
    if (lane == 0) cs[w] = part;
  }
  __syncthreads();

  // new_proto + blend: row-outer loop, 4 independent column streams (MLP)
  {
    float a[4][WAYS];
    #pragma unroll
    for (int d = 0; d < 4; d++)
      #pragma unroll
      for (int k = 0; k < WAYS; k++) a[d][k] = 0.f;
    #pragma unroll 2
    for (int i = 0; i < NF; i++) {
      const float* fr = (i < NSUP) ? (xsr + i * DIM)
                                   : (xqr + (size_t)(i - NSUP) * DIM);
      float f0 = fr[tid], f1 = fr[tid + 160], f2 = fr[tid + 320], f3 = fr[tid + 480];
      #pragma unroll
      for (int k = 0; k < WAYS; k++) {
        float z = Z[i][k];
        a[0][k] += z * f0; a[1][k] += z * f1; a[2][k] += z * f2; a[3][k] += z * f3;
      }
    }
    #pragma unroll
    for (int d = 0; d < 4; d++) {
      int dcol = tid + d * 160;
      #pragma unroll
      for (int k = 0; k < WAYS; k++) {
        float np = a[d][k] / cs[k];
        float pr = 0.4f * g_proto[run][k][dcol] + 0.6f * np;
        g_proto[run][k][dcol] = pr;
        psh[k][dcol] = pr;
      }
    }
  }
  __syncthreads();

  { // new proto norms (warp w -> class w); needed by both branches
    float a = 0.f;
    for (int d = lane; d < DIM; d += 32) { float v = psh[w][d]; a += v * v; }
    a = wred(a);
    if (lane == 0) pn2[w] = a;
  }
  __syncthreads();

  if (epoch < 2) {
    // ---- fused "ka" for epoch e+1: Pq from psh, then pass-1 ----
    for (int q = w; q < NQ; q += 5) {
      float a0=0,a1=0,a2=0,a3=0,a4=0,an=0;
      const float* xr = xqr + q * DIM;
      #pragma unroll 4
      for (int d = lane; d < DIM; d += 32) {
        float x = xr[d];
        an += x*x;
        a0 += x*psh[0][d]; a1 += x*psh[1][d]; a2 += x*psh[2][d];
        a3 += x*psh[3][d]; a4 += x*psh[4][d];
      }
      an = wred(an); a0 = wred(a0); a1 = wred(a1); a2 = wred(a2); a3 = wred(a3); a4 = wred(a4);
      if (lane == 0) {
        float acc[5] = {a0,a1,a2,a3,a4};
        #pragma unroll
        for (int k = 0; k < WAYS; k++) {
          float d2 = fmaxf(an + pn2[k] - 2.0f * acc[k], 0.0f);
          Psh[q][k] = expf(-LAM * d2);
        }
      }
    }
    __syncthreads();
    if (tid < 32) {
      float P[3][WAYS];
      #pragma unroll
      for (int s = 0; s < 3; s++) {
        int row = lane + 32 * s;
        #pragma unroll
        for (int k = 0; k < WAYS; k++) P[s][k] = (row < NQ) ? Psh[row][k] : 0.f;
      }
      int b = sink_pass1<3, NQ, false>(P, 15.0f, lane, 0);
      #pragma unroll
      for (int s = 0; s < 3; s++) {
        int row = lane + 32 * s;
        if (row < NQ)
          #pragma unroll
          for (int k = 0; k < WAYS; k++) g_P1[run][row][k] = P[s][k];
      }
      if (lane == 0) wbuf[run] = b;
    }
  } else {
    // ---- epoch-2 tail: proto distance graph, mask, Fp/Zext ----
    for (int p = w; p < WAYS * WAYS; p += 5) {
      int ia = p / WAYS, ib = p % WAYS;
      float acc = 0.f;
      for (int d = lane; d < DIM; d += 32) acc += psh[ia][d] * psh[ib][d];
      acc = wred(acc);
      if (lane == 0) {
        float d2 = fmaxf(pn2[ia] + pn2[ib] - 2.0f * acc, 0.0f);
        dp[ia][ib] = expf(-LAM * d2);
      }
    }
    __syncthreads();
    if (tid < WAYS) {
      float p[WAYS], s = 0.f;
      #pragma unroll
      for (int k = 0; k < WAYS; k++) { p[k] = dp[tid][k] + 1e-12f; s += p[k]; }
      float H = 0.f;
      #pragma unroll
      for (int k = 0; k < WAYS; k++) { float q = p[k] / s; H -= q * logf(q); }
      score[tid] = H / logf(5.0f);
    }
    if (w == 0) { // omega = mean(ent)
      float part = 0.f;
      for (int i = lane; i < NF; i += 32) part += ent[i];
      part = wred(part);
      if (lane == 0) omega_s = part / 100.0f;
    }
    __syncthreads();
    if (tid < WAYS) maskv[tid] = (score[tid] < omega_s) ? 1.0f : 0.0f;
    __syncthreads();
    for (int idx = tid; idx < WAYS * DIM; idx += 160) {
      int k = idx / DIM, d = idx % DIM;
      g_Fp[run][k][d] = psh[k][d] * maskv[k];
    }
    for (int idx = tid; idx < NF * WAYS; idx += 160) {
      int i = idx / WAYS, k = idx % WAYS;
      g_Zext[run][i][k] = Z[i][k];
    }
    if (tid < WAYS * WAYS) {
      int ia = tid / WAYS, k = tid % WAYS;
      g_Zext[run][NF + ia][k] = dp[ia][k] * maskv[ia];
    }
  }
}

// ---------------- KC1: symmetric Gram + graph + register Cholesky + solves -
#define FROWS 112
#define KCHUNK 64
#define FPAD 65
#define KC_SMEM (NTOT * NTOT * 4)   // 44,100B (>= FROWS*FPAD*4 = 29,120B)

__global__ __launch_bounds__(256, 2) void kc1_kernel(const float* __restrict__ xs,
                                                     const float* __restrict__ xq) {
  extern __shared__ float sm[];
  float* Fsh = sm;                  // phase 1 (Gram)
  float* As  = sm;                  // phase 2 (S matrix; Fsh dead)
  float* Lsh = sm;                  // phase 3 (L; As dead)
  __shared__ float n2[FROWS];
  __shared__ float rsum[FROWS];
  __shared__ float Dm[FROWS];
  __shared__ float colbuf[2][FROWS];
  __shared__ float sh_piv;
  __shared__ float yv[NTOT][WAYS];

  int run = blockIdx.x, tid = threadIdx.x;
  int ti = tid >> 4, tj = tid & 15;      // grid mapping (Cholesky phase)
  int w = tid >> 5, lane = tid & 31;
  const float* xsr = xs + (size_t)run * NSUP * DIM;
  const float* xqr = xq + (size_t)run * NQ * DIM;

  // triangular tile mapping for the Gram: threads 0..135 own tiles ti>=tj
  bool act = tid < 136;
  int tix = 0, tjx = 0;
  if (act) {
    tix = (int)((sqrtf(8.0f * (float)tid + 1.0f) - 1.0f) * 0.5f);
    while ((tix + 1) * (tix + 2) / 2 <= tid) tix++;
    while (tix * (tix + 1) / 2 > tid) tix--;
    tjx = tid - tix * (tix + 1) / 2;
  }

  float acc[7][7];
  #pragma unroll
  for (int r = 0; r < 7; r++)
    #pragma unroll
    for (int c = 0; c < 7; c++) acc[r][c] = 0.f;

  // ---- Gram (lower-triangle tiles only) ----
  for (int c0 = 0; c0 < DIM; c0 += KCHUNK) {
    __syncthreads();
    for (int e = tid; e < FROWS * KCHUNK; e += 256) {
      int r = e >> 6, dd = e & 63;
      float v = 0.f;
      if (r < NSUP)       v = xsr[r * DIM + c0 + dd];
      else if (r < NF)    v = xqr[(r - NSUP) * DIM + c0 + dd];
      else if (r < NTOT)  v = g_Fp[run][r - NF][c0 + dd];
      Fsh[r * FPAD + dd] = v;
    }
    __syncthreads();
    if (act) {
      #pragma unroll 4
      for (int dd = 0; dd < KCHUNK; dd++) {
        float a[7], bv[7];
        #pragma unroll
        for (int r = 0; r < 7; r++) a[r] = Fsh[(tix * 7 + r) * FPAD + dd];
        #pragma unroll
        for (int c = 0; c < 7; c++) bv[c] = Fsh[(tjx * 7 + c) * FPAD + dd];
        #pragma unroll
        for (int r = 0; r < 7; r++)
          #pragma unroll
          for (int c = 0; c < 7; c++) acc[r][c] += a[r] * bv[c];
      }
    }
  }
  __syncthreads();

  // ---- materialize S (both halves) in shared ----
  if (act) {
    #pragma unroll
    for (int r = 0; r < 7; r++) {
      int gi = tix * 7 + r;
      #pragma unroll
      for (int c = 0; c < 7; c++) {
        int gj = tjx * 7 + c;
        if (gi < NTOT && gj < NTOT) As[gi * NTOT + gj] = acc[r][c];
      }
    }
    if (tix > tjx) {
      #pragma unroll
      for (int r = 0; r < 7; r++) {
        int gi = tix * 7 + r;
        #pragma unroll
        for (int c = 0; c < 7; c++) {
          int gj = tjx * 7 + c;
          if (gi < NTOT && gj < NTOT) As[gj * NTOT + gi] = acc[r][c];
        }
      }
    }
  }
  __syncthreads();

  // ---- diag norms ----
  if (tid < FROWS) {
    n2[tid] = (tid < NTOT) ? As[tid * NTOT + tid] : 0.f;
    rsum[tid] = 0.f;
  }
  __syncthreads();

  // ---- every thread takes its GRID tile: W = exp(-LAM*d2), rowsums --------
  #pragma unroll
  for (int r = 0; r < 7; r++) {
    int gi = ti * 7 + r;
    #pragma unroll
    for (int c = 0; c < 7; c++) {
      int gj = tj * 7 + c;
      float wv = 0.f;
      if (gi < NTOT && gj < NTOT && gi != gj) {
        float d2 = fmaxf(n2[gi] + n2[gj] - 2.0f * As[gi * NTOT + gj], 0.0f);
        wv = expf(-LAM * d2);
      }
      acc[r][c] = wv;
    }
  }
  #pragma unroll
  for (int r = 0; r < 7; r++) {
    int gi = ti * 7 + r;
    float p = 0.f;
    #pragma unroll
    for (int c = 0; c < 7; c++) p += acc[r][c];
    if (gi < NTOT) atomicAdd(&rsum[gi], p);
  }
  __syncthreads();
  if (tid < FROWS) Dm[tid] = (tid < NTOT) ? (1.0f / sqrtf(rsum[tid])) : 0.f;
  __syncthreads();

  // ---- A = I - ALPHA * Dm_i W Dm_j (in registers) ----
  #pragma unroll
  for (int r = 0; r < 7; r++) {
    int gi = ti * 7 + r;
    float di = Dm[gi];
    #pragma unroll
    for (int c = 0; c < 7; c++) {
      int gj = tj * 7 + c;
      acc[r][c] = ((gi == gj) ? 1.0f : 0.0f) - ALPHA_ * di * acc[r][c] * Dm[gj];
    }
  }
  __syncthreads();

  // ---- register-resident Cholesky, rank-1 updates via shared column bcast --
  for (int jt = 0; jt < 15; jt++) {
    #pragma unroll
    for (int jc = 0; jc < 7; jc++) {
      int j = jt * 7 + jc;
      int buf = j & 1;
      if (tid < FROWS) colbuf[buf][tid] = 0.f;
      if (ti == jt && tj == jt) {
        float pv = sqrtf(acc[jc][jc]);
        acc[jc][jc] = pv;
        sh_piv = pv;
      }
      __syncthreads();
      if (tj == jt) {
        float ip = 1.0f / sh_piv;
        #pragma unroll
        for (int r = 0; r < 7; r++) {
          int gi = ti * 7 + r;
          if (gi > j) { acc[r][jc] *= ip; colbuf[buf][gi] = acc[r][jc]; }
        }
      }
      __syncthreads();
      float rv[7], cv[7];
      #pragma unroll
      for (int r = 0; r < 7; r++) rv[r] = colbuf[buf][ti * 7 + r];
      #pragma unroll
      for (int c = 0; c < 7; c++) cv[c] = colbuf[buf][tj * 7 + c];
      #pragma unroll
      for (int r = 0; r < 7; r++)
        #pragma unroll
        for (int c = 0; c < 7; c++) acc[r][c] -= rv[r] * cv[c];
    }
  }
  __syncthreads();   // As region dead; reuse as Lsh

  // ---- dump L (lower + diag) to shared ----
  #pragma unroll
  for (int r = 0; r < 7; r++) {
    int gi = ti * 7 + r;
    #pragma unroll
    for (int c = 0; c < 7; c++) {
      int gj = tj * 7 + c;
      if (gi < NTOT && gj < NTOT && gj <= gi) Lsh[gi * NTOT + gj] = acc[r][c];
    }
  }
  for (int idx = tid; idx < NTOT * WAYS; idx += 256)
    ((float*)yv)[idx] = ((const float*)g_Zext[run])[idx];
  __syncthreads();

  // ---- triangular solves: warp w handles RHS column w ----
  if (w < WAYS) {
    for (int i = 0; i < NTOT; i++) {
      float part = 0.f;
      for (int jj = lane; jj < i; jj += 32) part += Lsh[i * NTOT + jj] * yv[jj][w];
      part = wred(part);
      if (lane == 0) yv[i][w] = (yv[i][w] - part) / Lsh[i * NTOT + i];
      __syncwarp();
    }
    for (int i = NTOT - 1; i >= 0; i--) {
      float part = 0.f;
      for (int jj = i + 1 + lane; jj < NTOT; jj += 32) part += Lsh[jj * NTOT + i] * yv[jj][w];
      part = wred(part);
      if (lane == 0) yv[i][w] = (yv[i][w] - part) / Lsh[i * NTOT + i];
      __syncwarp();
    }
  }
  __syncthreads();

  // ---- write solved Z; sinkhorn2 runs in kc2 ----
  for (int idx = tid; idx < NTOT * WAYS; idx += 256)
    ((float*)g_Z0[run])[idx] = ((const float*)yv)[idx];
}

// ---------------- KC2: sinkhorn2 pass-1, 1 warp per run ---------------------
__global__ __launch_bounds__(128) void kc2_kernel(const int* __restrict__ ys) {
  int tid = threadIdx.x, w = tid >> 5, lane = tid & 31;
  int run = blockIdx.x * 4 + w;
  const int* ysr = ys + run * NSUP;
  float P[4][WAYS];
  #pragma unroll
  for (int s = 0; s < 4; s++) {
    int row = lane + 32 * s;
    #pragma unroll
    for (int k = 0; k < WAYS; k++) P[s][k] = (row < NTOT) ? g_Z0[run][row][k] : 0.f;
  }
  int cls = (lane < NSUP) ? ysr[lane] : 0;
  int b = sink_pass1<4, NTOT, true>(P, 21.0f, lane, cls);
  #pragma unroll
  for (int s = 0; s < 4; s++) {
    int row = lane + 32 * s;
    if (row < NTOT)
      #pragma unroll
      for (int k = 0; k < WAYS; k++) g_Z0[run][row][k] = P[s][k];
  }
  if (lane == 0) g_b2run[run] = b;
}

// ---------------- KD: 1 warp per run: replay sinkhorn2, argmax, accuracy ----
__global__ __launch_bounds__(128) void kd_kernel(const int* __restrict__ ys,
                                                 const int* __restrict__ yq,
                                                 float* __restrict__ out) {
  int tid = threadIdx.x, w = tid >> 5, lane = tid & 31;
  int run = blockIdx.x * 4 + w;
  const int* ysr = ys + run * NSUP;
  float P[4][WAYS];
  #pragma unroll
  for (int s = 0; s < 4; s++) {
    int row = lane + 32 * s;
    #pragma unroll
    for (int k = 0; k < WAYS; k++) P[s][k] = (row < NTOT) ? g_Z0[run][row][k] : 0.f;
  }
  int cls = (lane < NSUP) ? ysr[lane] : 0;
  int m = 0;
  for (int i = lane; i < RUNS; i += 32) m = max(m, g_b2run[i]);
  m = __reduce_max_sync(0xffffffffu, m);
  int extra = m - g_b2run[run];
  sink_replay<4, NTOT, true>(P, 21.0f, lane, cls, extra);

  int cnt = 0;
  #pragma unroll
  for (int s = 0; s < 4; s++) {
    int row = lane + 32 * s;
    if (row >= NSUP && row < NF) {
      float best = P[s][0]; int bi = 0;
      #pragma unroll
      for (int k = 1; k < WAYS; k++)
        if (P[s][k] > best) { best = P[s][k]; bi = k; }
      if (bi == yq[run * NQ + (row - NSUP)]) cnt++;
    }
  }
  #pragma unroll
  for (int o = 16; o; o >>= 1) cnt += __shfl_xor_sync(0xffffffffu, cnt, o);
  if (lane == 0) out[run] = (float)cnt / 75.0f;
}

// ---------------------------------------------------------------------------
extern "C" void kernel_launch(void* const* d_in, const int* in_sizes, int n_in,
                              void* d_out, int out_size) {
  const float* xs = (const float*)d_in[0];
  const float* xq = (const float*)d_in[1];
  const int*   ys = (const int*)d_in[2];
  const int*   yq = (const int*)d_in[3];
  float* out = (float*)d_out;

  cudaFuncSetAttribute(kc1_kernel, cudaFuncAttributeMaxDynamicSharedMemorySize,
                       KC_SMEM);

  ka_kernel<<<RUNS, 160>>>(xs, xq);
  for (int e = 0; e < 3; e++)
    kb_kernel<<<RUNS, 160>>>(xs, xq, ys, e);
  kc1_kernel<<<RUNS, 256, KC_SMEM>>>(xs, xq);
  kc2_kernel<<<RUNS / 4, 128>>>(ys);
  kd_kernel<<<RUNS / 4, 128>>>(ys, yq, out);
}

// round 10
// speedup vs baseline: 1.7297x; 1.0987x over previous
#include <cuda_runtime.h>
#include <math.h>
#include <stdint.h>

#define RUNS 512
#define WAYS 5
#define SHOT 5
#define NSUP 25
#define NQ   75
#define NF   100
#define NTOT 105
#define DIM  640
#define LAM  10.0f
#define ALPHA_ 0.7f
#define EPSV 1e-3f
#define MAXIT 1000

// ---------------- device scratch (static: no allocations allowed) ----------
__device__ float g_proto[RUNS][WAYS][DIM];
__device__ float g_Fp[RUNS][WAYS][DIM];     // masked proto rows (epoch 2)
__device__ float g_P1[RUNS][NQ][WAYS];      // sinkhorn1 state after pass-1
__device__ int   g_b1A[RUNS];               // per-run body counts (double buf)
__device__ int   g_b1B[RUNS];
__device__ float g_Zext[RUNS][NTOT][WAYS];  // extended Z (epoch 2, pre-solve)
__device__ float g_Z0[RUNS][NTOT][WAYS];    // solved Z / sinkhorn2 state
__device__ int   g_b2run[RUNS];

__device__ __forceinline__ float wred(float v) {
  #pragma unroll
  for (int o = 16; o; o >>= 1) v += __shfl_down_sync(0xffffffffu, v, o);
  return v;
}
__device__ __forceinline__ float wsum_x(float v) {
  #pragma unroll
  for (int o = 16; o; o >>= 1) v += __shfl_xor_sync(0xffffffffu, v, o);
  return v;
}
__device__ __forceinline__ float wmax_x(float v) {
  #pragma unroll
  for (int o = 16; o; o >>= 1) v = fmaxf(v, __shfl_xor_sync(0xffffffffu, v, o));
  return v;
}
__device__ __forceinline__ float fdiv(float a, float b) { return __fdividef(a, b); }

// ---- single-warp register sinkhorn: pass-1 (count bodies to own converge) --
template<int NR, int NROWS, bool LAB>
__device__ __forceinline__ int sink_pass1(float (&P)[NR][WAYS], float ctot,
                                          int lane, int cls) {
  float u[NR];
  #pragma unroll
  for (int s = 0; s < NR; s++) u[s] = 0.f;
  int b = 0;
  for (;;) {
    float rs[NR];
    float d = 0.f;
    #pragma unroll
    for (int s = 0; s < NR; s++) {
      rs[s] = P[s][0] + P[s][1] + P[s][2] + P[s][3] + P[s][4];
      if (lane + 32 * s < NROWS) d = fmaxf(d, fabsf(u[s] - rs[s]));
    }
    float delta = wmax_x(d);
    float t[NR][WAYS];
    float cp[WAYS] = {0.f, 0.f, 0.f, 0.f, 0.f};
    #pragma unroll
    for (int s = 0; s < NR; s++) {
      float inv = (lane + 32 * s < NROWS) ? fdiv(1.0f, rs[s]) : 0.f;
      #pragma unroll
      for (int k = 0; k < WAYS; k++) { t[s][k] = P[s][k] * inv; cp[k] += t[s][k]; }
    }
    float f[WAYS];
    #pragma unroll
    for (int k = 0; k < WAYS; k++) f[k] = fdiv(ctot, wsum_x(cp[k]));
    #pragma unroll
    for (int s = 0; s < NR; s++)
      #pragma unroll
      for (int k = 0; k < WAYS; k++) t[s][k] *= f[k];
    if (LAB && lane < NSUP) {
      #pragma unroll
      for (int k = 0; k < WAYS; k++) t[0][k] = (k == cls) ? 1.f : 0.f;
    }
    if (!(delta > EPSV && b < MAXIT)) break;
    #pragma unroll
    for (int s = 0; s < NR; s++) {
      u[s] = rs[s];
      #pragma unroll
      for (int k = 0; k < WAYS; k++) P[s][k] = t[s][k];
    }
    b++;
  }
  return b;
}

// ---- single-warp register sinkhorn: replay exactly `iters` bodies ----------
template<int NR, int NROWS, bool LAB>
__device__ __forceinline__ void sink_replay(float (&P)[NR][WAYS], float ctot,
                                            int lane, int cls, int iters) {
  for (int it = 0; it < iters; it++) {
    float cp[WAYS] = {0.f, 0.f, 0.f, 0.f, 0.f};
    #pragma unroll
    for (int s = 0; s < NR; s++) {
      float rs = P[s][0] + P[s][1] + P[s][2] + P[s][3] + P[s][4];
      float inv = (lane + 32 * s < NROWS) ? fdiv(1.0f, rs) : 0.f;
      #pragma unroll
      for (int k = 0; k < WAYS; k++) { P[s][k] *= inv; cp[k] += P[s][k]; }
    }
    float f[WAYS];
    #pragma unroll
    for (int k = 0; k < WAYS; k++) f[k] = fdiv(ctot, wsum_x(cp[k]));
    #pragma unroll
    for (int s = 0; s < NR; s++)
      #pragma unroll
      for (int k = 0; k < WAYS; k++) P[s][k] *= f[k];
    if (LAB && lane < NSUP) {
      #pragma unroll
      for (int k = 0; k < WAYS; k++) P[0][k] = (k == cls) ? 1.f : 0.f;
    }
  }
}

// ---------------- KA: epoch-0 proto, Pq0, sinkhorn1 pass-1 ------------------
__global__ __launch_bounds__(160) void ka_kernel(const float* __restrict__ xs,
                                                 const float* __restrict__ xq) {
  __shared__ float ps[WAYS][DIM];
  __shared__ float pn[WAYS];
  __shared__ float Psh[NQ][WAYS];
  int run = blockIdx.x;
  int tid = threadIdx.x, w = tid >> 5, lane = tid & 31;
  const float* xsr = xs + (size_t)run * NSUP * DIM;
  const float* xqr = xq + (size_t)run * NQ * DIM;

  for (int idx = tid; idx < WAYS * DIM; idx += 160) {
    int k = idx / DIM, d = idx % DIM;
    float s = 0.f;
    #pragma unroll
    for (int sh = 0; sh < SHOT; sh++) s += xsr[(k * SHOT + sh) * DIM + d];
    float v = s / 5.0f;
    ps[k][d] = v;
    g_proto[run][k][d] = v;
  }
  __syncthreads();

  { // proto norms (warp w does class w)
    float a = 0.f;
    for (int d = lane; d < DIM; d += 32) { float v = ps[w][d]; a += v * v; }
    a = wred(a);
    if (lane == 0) pn[w] = a;
  }
  __syncthreads();

  // Pq = exp(-LAM * d2(query, proto))
  for (int q = w; q < NQ; q += 5) {
    float a0=0,a1=0,a2=0,a3=0,a4=0,an=0;
    const float* xr = xqr + q * DIM;
    #pragma unroll 4
    for (int d = lane; d < DIM; d += 32) {
      float x = xr[d];
      an += x*x;
      a0 += x*ps[0][d]; a1 += x*ps[1][d]; a2 += x*ps[2][d];
      a3 += x*ps[3][d]; a4 += x*ps[4][d];
    }
    an = wred(an); a0 = wred(a0); a1 = wred(a1); a2 = wred(a2); a3 = wred(a3); a4 = wred(a4);
    if (lane == 0) {
      float acc[5] = {a0,a1,a2,a3,a4};
      #pragma unroll
      for (int k = 0; k < WAYS; k++) {
        float d2 = fmaxf(an + pn[k] - 2.0f * acc[k], 0.0f);
        Psh[q][k] = expf(-LAM * d2);
      }
    }
  }
  __syncthreads();

  if (tid < 32) {
    float P[3][WAYS];
    #pragma unroll
    for (int s = 0; s < 3; s++) {
      int row = lane + 32 * s;
      #pragma unroll
      for (int k = 0; k < WAYS; k++) P[s][k] = (row < NQ) ? Psh[row][k] : 0.f;
    }
    int b = sink_pass1<3, NQ, false>(P, 15.0f, lane, 0);
    #pragma unroll
    for (int s = 0; s < 3; s++) {
      int row = lane + 32 * s;
      if (row < NQ)
        #pragma unroll
        for (int k = 0; k < WAYS; k++) g_P1[run][row][k] = P[s][k];
    }
    if (lane == 0) g_b1A[run] = b;
  }
}

// ---- KB (fused): replay sinkhorn1(e), entropy, blend; then either
//      Pq+pass-1 for epoch e+1 (e<2) or the epoch-2 tail (Fp/Zext). ---------
__global__ __launch_bounds__(160) void kb_kernel(const float* __restrict__ xs,
                                                 const float* __restrict__ xq,
                                                 const int* __restrict__ ys,
                                                 int epoch) {
  __shared__ float Psh[NQ][WAYS];
  __shared__ float Z[NF][WAYS];
  __shared__ float ent[NF];
  __shared__ float cs[WAYS];
  __shared__ float psh[WAYS][DIM];
  __shared__ float pn2[WAYS];
  __shared__ float dp[WAYS][WAYS];
  __shared__ float score[WAYS], maskv[WAYS];
  __shared__ float omega_s;
  int run = blockIdx.x, tid = threadIdx.x;
  int w = tid >> 5, lane = tid & 31;
  const int* ysr = ys + run * NSUP;
  const float* xsr = xs + (size_t)run * NSUP * DIM;
  const float* xqr = xq + (size_t)run * NQ * DIM;

  const int* rbuf = (epoch == 1) ? g_b1B : g_b1A;   // pass-1 counts for epoch e
  int* wbuf = (epoch == 0) ? g_b1B : g_b1A;          // counts for epoch e+1

  if (tid < 32) {  // warp 0: replay to global B, registers only
    float P[3][WAYS];
    #pragma unroll
    for (int s = 0; s < 3; s++) {
      int row = lane + 32 * s;
      #pragma unroll
      for (int k = 0; k < WAYS; k++) P[s][k] = (row < NQ) ? g_P1[run][row][k] : 0.f;
    }
    int m = 0;
    for (int i = lane; i < RUNS; i += 32) m = max(m, rbuf[i]);
    m = __reduce_max_sync(0xffffffffu, m);
    int extra = m - rbuf[run];
    sink_replay<3, NQ, false>(P, 15.0f, lane, 0, extra);
    #pragma unroll
    for (int s = 0; s < 3; s++) {
      int row = lane + 32 * s;
      if (row < NQ)
        #pragma unroll
        for (int k = 0; k < WAYS; k++) Psh[row][k] = P[s][k];
    }
  } else {
    // warps 1-4: prefetch the feature block to L2 while warp 0 replays
    int t4 = (w - 1) * 32 + lane;   // 0..127
    for (int off = t4 * 32; off < NSUP * DIM; off += 128 * 32)
      asm volatile("prefetch.global.L2 [%0];" :: "l"(xsr + off));
    for (int off = t4 * 32; off < NQ * DIM; off += 128 * 32)
      asm volatile("prefetch.global.L2 [%0];" :: "l"(xqr + off));
  }
  __syncthreads();

  // Z = [onehot(ys); Pq]
  for (int idx = tid; idx < NF * WAYS; idx += 160) {
    int i = idx / WAYS, k = idx % WAYS;
    float v = (i < NSUP) ? ((ysr[i] == k) ? 1.0f : 0.0f) : Psh[i - NSUP][k];
    Z[i][k] = v;
  }
  __syncthreads();

  // entropy per row
  if (tid < NF) {
    float p[WAYS], s = 0.f;
    #pragma unroll
    for (int k = 0; k < WAYS; k++) { p[k] = Z[tid][k] + 1e-12f; s += p[k]; }
    float H = 0.f;
    #pragma unroll
    for (int k = 0; k < WAYS; k++) { float q = p[k] / s; H -= q * logf(q); }
    ent[tid] = H / logf(5.0f);
  }
  __syncthreads();

  // Z *= (1 - ent)
  for (int idx = tid; idx < NF * WAYS; idx += 160) {
    int i = idx / WAYS;
    ((float*)Z)[idx] *= (1.0f - ent[i]);
  }
  __syncthreads();
  { // column sums via warp reductions (warp w -> class w)
    float part = 0.f;
    for (int i = lane; i < NF; i += 32) part += Z[i][w];
    part = wred(part);
    if (lane == 0) cs[w] = part;
  }
  __syncthreads();

  // new_proto + blend: row-outer loop, 4 independent column streams (MLP)
  {
    float a[4][WAYS];
    #pragma unroll
    for (int d = 0; d < 4; d++)
      #pragma unroll
      for (int k = 0; k < WAYS; k++) a[d][k] = 0.f;
    #pragma unroll 2
    for (int i = 0; i < NF; i++) {
      const float* fr = (i < NSUP) ? (xsr + i * DIM)
                                   : (xqr + (size_t)(i - NSUP) * DIM);
      float f0 = fr[tid], f1 = fr[tid + 160], f2 = fr[tid + 320], f3 = fr[tid + 480];
      #pragma unroll
      for (int k = 0; k < WAYS; k++) {
        float z = Z[i][k];
        a[0][k] += z * f0; a[1][k] += z * f1; a[2][k] += z * f2; a[3][k] += z * f3;
      }
    }
    #pragma unroll
    for (int d = 0; d < 4; d++) {
      int dcol = tid + d * 160;
      #pragma unroll
      for (int k = 0; k < WAYS; k++) {
        float np = a[d][k] / cs[k];
        float pr = 0.4f * g_proto[run][k][dcol] + 0.6f * np;
        g_proto[run][k][dcol] = pr;
        psh[k][dcol] = pr;
      }
    }
  }
  __syncthreads();

  { // new proto norms (warp w -> class w); needed by both branches
    float a = 0.f;
    for (int d = lane; d < DIM; d += 32) { float v = psh[w][d]; a += v * v; }
    a = wred(a);
    if (lane == 0) pn2[w] = a;
  }
  __syncthreads();

  if (epoch < 2) {
    // ---- fused "ka" for epoch e+1: Pq from psh, then pass-1 ----
    for (int q = w; q < NQ; q += 5) {
      float a0=0,a1=0,a2=0,a3=0,a4=0,an=0;
      const float* xr = xqr + q * DIM;
      #pragma unroll 4
      for (int d = lane; d < DIM; d += 32) {
        float x = xr[d];
        an += x*x;
        a0 += x*psh[0][d]; a1 += x*psh[1][d]; a2 += x*psh[2][d];
        a3 += x*psh[3][d]; a4 += x*psh[4][d];
      }
      an = wred(an); a0 = wred(a0); a1 = wred(a1); a2 = wred(a2); a3 = wred(a3); a4 = wred(a4);
      if (lane == 0) {
        float acc[5] = {a0,a1,a2,a3,a4};
        #pragma unroll
        for (int k = 0; k < WAYS; k++) {
          float d2 = fmaxf(an + pn2[k] - 2.0f * acc[k], 0.0f);
          Psh[q][k] = expf(-LAM * d2);
        }
      }
    }
    __syncthreads();
    if (tid < 32) {
      float P[3][WAYS];
      #pragma unroll
      for (int s = 0; s < 3; s++) {
        int row = lane + 32 * s;
        #pragma unroll
        for (int k = 0; k < WAYS; k++) P[s][k] = (row < NQ) ? Psh[row][k] : 0.f;
      }
      int b = sink_pass1<3, NQ, false>(P, 15.0f, lane, 0);
      #pragma unroll
      for (int s = 0; s < 3; s++) {
        int row = lane + 32 * s;
        if (row < NQ)
          #pragma unroll
          for (int k = 0; k < WAYS; k++) g_P1[run][row][k] = P[s][k];
      }
      if (lane == 0) wbuf[run] = b;
    }
  } else {
    // ---- epoch-2 tail: proto distance graph, mask, Fp/Zext ----
    for (int p = w; p < WAYS * WAYS; p += 5) {
      int ia = p / WAYS, ib = p % WAYS;
      float acc = 0.f;
      for (int d = lane; d < DIM; d += 32) acc += psh[ia][d] * psh[ib][d];
      acc = wred(acc);
      if (lane == 0) {
        float d2 = fmaxf(pn2[ia] + pn2[ib] - 2.0f * acc, 0.0f);
        dp[ia][ib] = expf(-LAM * d2);
      }
    }
    __syncthreads();
    if (tid < WAYS) {
      float p[WAYS], s = 0.f;
      #pragma unroll
      for (int k = 0; k < WAYS; k++) { p[k] = dp[tid][k] + 1e-12f; s += p[k]; }
      float H = 0.f;
      #pragma unroll
      for (int k = 0; k < WAYS; k++) { float q = p[k] / s; H -= q * logf(q); }
      score[tid] = H / logf(5.0f);
    }
    if (w == 0) { // omega = mean(ent)
      float part = 0.f;
      for (int i = lane; i < NF; i += 32) part += ent[i];
      part = wred(part);
      if (lane == 0) omega_s = part / 100.0f;
    }
    __syncthreads();
    if (tid < WAYS) maskv[tid] = (score[tid] < omega_s) ? 1.0f : 0.0f;
    __syncthreads();
    for (int idx = tid; idx < WAYS * DIM; idx += 160) {
      int k = idx / DIM, d = idx % DIM;
      g_Fp[run][k][d] = psh[k][d] * maskv[k];
    }
    for (int idx = tid; idx < NF * WAYS; idx += 160) {
      int i = idx / WAYS, k = idx % WAYS;
      g_Zext[run][i][k] = Z[i][k];
    }
    if (tid < WAYS * WAYS) {
      int ia = tid / WAYS, k = tid % WAYS;
      g_Zext[run][NF + ia][k] = dp[ia][k] * maskv[ia];
    }
  }
}

// ---------------- KC1: f32x2 Gram + graph + register Cholesky + fast solves
#define FROWS 112
#define KCHUNK 64
#define FPAD 66                      // even: 8B-aligned LDS.64 pairs
#define NT6 18                       // ceil(105/6) tile rows (6x6 tiles)
#define NTRI (NT6 * (NT6 + 1) / 2)   // 171 triangular tiles
#define KC_SMEM (NTOT * NTOT * 4)    // 44,100B (>= FROWS*FPAD*4 = 29,568B)

__global__ __launch_bounds__(256, 2) void kc1_kernel(const float* __restrict__ xs,
                                                     const float* __restrict__ xq) {
  extern __shared__ float sm[];
  float* Fsh = sm;                  // phase 1 (Gram)
  float* As  = sm;                  // phase 2 (S matrix; Fsh dead)
  float* Lsh = sm;                  // phase 3 (L; As dead)
  __shared__ float n2[FROWS];
  __shared__ float rsum[FROWS];
  __shared__ float Dm[FROWS];
  __shared__ float colbuf[2][FROWS];
  __shared__ float sh_piv;
  __shared__ float yv[NTOT][WAYS];

  int run = blockIdx.x, tid = threadIdx.x;
  int ti = tid >> 4, tj = tid & 15;      // 7x7 grid mapping (Cholesky phase)
  int w = tid >> 5, lane = tid & 31;
  const float* xsr = xs + (size_t)run * NSUP * DIM;
  const float* xqr = xq + (size_t)run * NQ * DIM;

  // triangular 6x6 tile mapping: threads 0..170 own tiles tix>=tjx
  bool act = tid < NTRI;
  int tix = 0, tjx = 0;
  if (act) {
    tix = (int)((sqrtf(8.0f * (float)tid + 1.0f) - 1.0f) * 0.5f);
    while ((tix + 1) * (tix + 2) / 2 <= tid) tix++;
    while (tix * (tix + 1) / 2 > tid) tix--;
    tjx = tid - tix * (tix + 1) / 2;
  }

  // ---- Gram (lower-triangle 6x6 tiles, f32x2 packed along K) ----
  unsigned long long acc2[6][6];
  #pragma unroll
  for (int r = 0; r < 6; r++)
    #pragma unroll
    for (int c = 0; c < 6; c++) acc2[r][c] = 0ull;

  for (int c0 = 0; c0 < DIM; c0 += KCHUNK) {
    __syncthreads();
    for (int e = tid; e < FROWS * KCHUNK; e += 256) {
      int r = e >> 6, dd = e & 63;
      float v = 0.f;
      if (r < NSUP)       v = xsr[r * DIM + c0 + dd];
      else if (r < NF)    v = xqr[(r - NSUP) * DIM + c0 + dd];
      else if (r < NTOT)  v = g_Fp[run][r - NF][c0 + dd];
      Fsh[r * FPAD + dd] = v;
    }
    __syncthreads();
    if (act) {
      #pragma unroll 4
      for (int dd = 0; dd < KCHUNK; dd += 2) {
        unsigned long long a2[6], b2[6];
        #pragma unroll
        for (int r = 0; r < 6; r++)
          a2[r] = *(const unsigned long long*)&Fsh[(tix * 6 + r) * FPAD + dd];
        #pragma unroll
        for (int c = 0; c < 6; c++)
          b2[c] = *(const unsigned long long*)&Fsh[(tjx * 6 + c) * FPAD + dd];
        #pragma unroll
        for (int r = 0; r < 6; r++)
          #pragma unroll
          for (int c = 0; c < 6; c++)
            asm("fma.rn.f32x2 %0, %1, %2, %0;"
                : "+l"(acc2[r][c]) : "l"(a2[r]), "l"(b2[c]));
      }
    }
  }
  __syncthreads();

  // ---- materialize S (both halves) in shared ----
  if (act) {
    #pragma unroll
    for (int r = 0; r < 6; r++) {
      int gi = tix * 6 + r;
      #pragma unroll
      for (int c = 0; c < 6; c++) {
        int gj = tjx * 6 + c;
        if (gi < NTOT && gj < NTOT) {
          float2 v2 = *(float2*)&acc2[r][c];
          float sv = v2.x + v2.y;
          As[gi * NTOT + gj] = sv;
          if (tix > tjx) As[gj * NTOT + gi] = sv;
        }
      }
    }
  }
  __syncthreads();

  // ---- diag norms ----
  if (tid < FROWS) {
    n2[tid] = (tid < NTOT) ? As[tid * NTOT + tid] : 0.f;
    rsum[tid] = 0.f;
  }
  __syncthreads();

  // ---- every thread takes its 7x7 GRID tile: W = exp(-LAM*d2), rowsums ----
  float acc[7][7];
  #pragma unroll
  for (int r = 0; r < 7; r++) {
    int gi = ti * 7 + r;
    #pragma unroll
    for (int c = 0; c < 7; c++) {
      int gj = tj * 7 + c;
      float wv = 0.f;
      if (gi < NTOT && gj < NTOT && gi != gj) {
        float d2 = fmaxf(n2[gi] + n2[gj] - 2.0f * As[gi * NTOT + gj], 0.0f);
        wv = expf(-LAM * d2);
      }
      acc[r][c] = wv;
    }
  }
  #pragma unroll
  for (int r = 0; r < 7; r++) {
    int gi = ti * 7 + r;
    float p = 0.f;
    #pragma unroll
    for (int c = 0; c < 7; c++) p += acc[r][c];
    if (gi < NTOT) atomicAdd(&rsum[gi], p);
  }
  __syncthreads();
  if (tid < FROWS) Dm[tid] = (tid < NTOT) ? (1.0f / sqrtf(rsum[tid])) : 0.f;
  __syncthreads();

  // ---- A = I - ALPHA * Dm_i W Dm_j (in registers) ----
  #pragma unroll
  for (int r = 0; r < 7; r++) {
    int gi = ti * 7 + r;
    float di = Dm[gi];
    #pragma unroll
    for (int c = 0; c < 7; c++) {
      int gj = tj * 7 + c;
      acc[r][c] = ((gi == gj) ? 1.0f : 0.0f) - ALPHA_ * di * acc[r][c] * Dm[gj];
    }
  }
  __syncthreads();

  // ---- register-resident Cholesky, rank-1 updates via shared column bcast --
  for (int jt = 0; jt < 15; jt++) {
    #pragma unroll
    for (int jc = 0; jc < 7; jc++) {
      int j = jt * 7 + jc;
      int buf = j & 1;
      if (tid < FROWS) colbuf[buf][tid] = 0.f;
      if (ti == jt && tj == jt) {
        float pv = sqrtf(acc[jc][jc]);
        acc[jc][jc] = pv;
        sh_piv = pv;
      }
      __syncthreads();
      if (tj == jt) {
        float ip = 1.0f / sh_piv;
        #pragma unroll
        for (int r = 0; r < 7; r++) {
          int gi = ti * 7 + r;
          if (gi > j) { acc[r][jc] *= ip; colbuf[buf][gi] = acc[r][jc]; }
        }
      }
      __syncthreads();
      float rv[7], cv[7];
      #pragma unroll
      for (int r = 0; r < 7; r++) rv[r] = colbuf[buf][ti * 7 + r];
      #pragma unroll
      for (int c = 0; c < 7; c++) cv[c] = colbuf[buf][tj * 7 + c];
      #pragma unroll
      for (int r = 0; r < 7; r++)
        #pragma unroll
        for (int c = 0; c < 7; c++) acc[r][c] -= rv[r] * cv[c];
    }
  }
  __syncthreads();   // As region dead; reuse as Lsh

  // ---- dump L (lower + diag) to shared ----
  #pragma unroll
  for (int r = 0; r < 7; r++) {
    int gi = ti * 7 + r;
    #pragma unroll
    for (int c = 0; c < 7; c++) {
      int gj = tj * 7 + c;
      if (gi < NTOT && gj < NTOT && gj <= gi) Lsh[gi * NTOT + gj] = acc[r][c];
    }
  }
  for (int idx = tid; idx < NTOT * WAYS; idx += 256)
    ((float*)yv)[idx] = ((const float*)g_Zext[run])[idx];
  __syncthreads();

  // ---- triangular solves: warp w owns RHS col w; shfl-broadcast sweep ----
  if (w < WAYS) {
    float rr[4], dinv[4];
    #pragma unroll
    for (int s = 0; s < 4; s++) {
      int row = lane + 32 * s;
      rr[s]   = (row < NTOT) ? yv[row][w] : 0.f;
      dinv[s] = (row < NTOT) ? (1.0f / Lsh[row * NTOT + row]) : 0.f;
    }
    // forward: L y = b
    for (int i = 0; i < NTOT; i++) {
      int s_i = i >> 5, src = i & 31;
      float yi = rr[s_i] * dinv[s_i];
      yi = __shfl_sync(0xffffffffu, yi, src);
      if (lane == src) rr[s_i] = yi;
      #pragma unroll
      for (int s = 0; s < 4; s++) {
        int row = lane + 32 * s;
        if (row > i && row < NTOT) rr[s] -= Lsh[row * NTOT + i] * yi;
      }
    }
    // backward: L^T x = y
    for (int i = NTOT - 1; i >= 0; i--) {
      int s_i = i >> 5, src = i & 31;
      float xi = rr[s_i] * dinv[s_i];
      xi = __shfl_sync(0xffffffffu, xi, src);
      if (lane == src) rr[s_i] = xi;
      #pragma unroll
      for (int s = 0; s < 4; s++) {
        int row = lane + 32 * s;
        if (row < i) rr[s] -= Lsh[i * NTOT + row] * xi;
      }
    }
    #pragma unroll
    for (int s = 0; s < 4; s++) {
      int row = lane + 32 * s;
      if (row < NTOT) yv[row][w] = rr[s];
    }
  }
  __syncthreads();

  // ---- write solved Z; sinkhorn2 runs in kc2 ----
  for (int idx = tid; idx < NTOT * WAYS; idx += 256)
    ((float*)g_Z0[run])[idx] = ((const float*)yv)[idx];
}

// ---------------- KC2: sinkhorn2 pass-1, 1 warp per run ---------------------
__global__ __launch_bounds__(128) void kc2_kernel(const int* __restrict__ ys) {
  int tid = threadIdx.x, w = tid >> 5, lane = tid & 31;
  int run = blockIdx.x * 4 + w;
  const int* ysr = ys + run * NSUP;
  float P[4][WAYS];
  #pragma unroll
  for (int s = 0; s < 4; s++) {
    int row = lane + 32 * s;
    #pragma unroll
    for (int k = 0; k < WAYS; k++) P[s][k] = (row < NTOT) ? g_Z0[run][row][k] : 0.f;
  }
  int cls = (lane < NSUP) ? ysr[lane] : 0;
  int b = sink_pass1<4, NTOT, true>(P, 21.0f, lane, cls);
  #pragma unroll
  for (int s = 0; s < 4; s++) {
    int row = lane + 32 * s;
    if (row < NTOT)
      #pragma unroll
      for (int k = 0; k < WAYS; k++) g_Z0[run][row][k] = P[s][k];
  }
  if (lane == 0) g_b2run[run] = b;
}

// ---------------- KD: 1 warp per run: replay sinkhorn2, argmax, accuracy ----
__global__ __launch_bounds__(128) void kd_kernel(const int* __restrict__ ys,
                                                 const int* __restrict__ yq,
                                                 float* __restrict__ out) {
  int tid = threadIdx.x, w = tid >> 5, lane = tid & 31;
  int run = blockIdx.x * 4 + w;
  const int* ysr = ys + run * NSUP;
  float P[4][WAYS];
  #pragma unroll
  for (int s = 0; s < 4; s++) {
    int row = lane + 32 * s;
    #pragma unroll
    for (int k = 0; k < WAYS; k++) P[s][k] = (row < NTOT) ? g_Z0[run][row][k] : 0.f;
  }
  int cls = (lane < NSUP) ? ysr[lane] : 0;
  int m = 0;
  for (int i = lane; i < RUNS; i += 32) m = max(m, g_b2run[i]);
  m = __reduce_max_sync(0xffffffffu, m);
  int extra = m - g_b2run[run];
  sink_replay<4, NTOT, true>(P, 21.0f, lane, cls, extra);

  int cnt = 0;
  #pragma unroll
  for (int s = 0; s < 4; s++) {
    int row = lane + 32 * s;
    if (row >= NSUP && row < NF) {
      float best = P[s][0]; int bi = 0;
      #pragma unroll
      for (int k = 1; k < WAYS; k++)
        if (P[s][k] > best) { best = P[s][k]; bi = k; }
      if (bi == yq[run * NQ + (row - NSUP)]) cnt++;
    }
  }
  #pragma unroll
  for (int o = 16; o; o >>= 1) cnt += __shfl_xor_sync(0xffffffffu, cnt, o);
  if (lane == 0) out[run] = (float)cnt / 75.0f;
}

// ---------------------------------------------------------------------------
extern "C" void kernel_launch(void* const* d_in, const int* in_sizes, int n_in,
                              void* d_out, int out_size) {
  const float* xs = (const float*)d_in[0];
  const float* xq = (const float*)d_in[1];
  const int*   ys = (const int*)d_in[2];
  const int*   yq = (const int*)d_in[3];
  float* out = (float*)d_out;

  cudaFuncSetAttribute(kc1_kernel, cudaFuncAttributeMaxDynamicSharedMemorySize,
                       KC_SMEM);

  ka_kernel<<<RUNS, 160>>>(xs, xq);
  for (int e = 0; e < 3; e++)
    kb_kernel<<<RUNS, 160>>>(xs, xq, ys, e);
  kc1_kernel<<<RUNS, 256, KC_SMEM>>>(xs, xq);
  kc2_kernel<<<RUNS / 4, 128>>>(ys);
  kd_kernel<<<RUNS / 4, 128>>>(ys, yq, out);
}